// round 1
// baseline (speedup 1.0000x reference)
#include <cuda_runtime.h>
#include <cuda_bf16.h>
#include <math.h>

#define HW 10000
#define H_IMG 100
#define W_IMG 100

// ---------------- scratch (static device globals; no allocation) -------------
__device__ float g_buf[1280000];   // conv outputs pre-norm (128ch)
__device__ float g_q[1280000];     // q after instance norm
__device__ float g_ref[240000];    // (hw, 8, 3) reference points
__device__ float g_swl[320000];    // (hw, 8, 4) softmax weights
__device__ float g_featT[2962080]; // channel-last features, 4 levels concat
__device__ float g_sf[2560000];    // folded features (256, 100, 100)
__device__ float g_m1[5120000];    // mid conv1 out (512ch)
__device__ float g_m2[5120000];    // mid conv2 out (512ch)

// level geometry
#define L0_OFF 0
#define L1_OFF 2230272
#define L2_OFF 2787840
#define L3_OFF 2927232

__device__ __forceinline__ float gelu_exact(float x) {
    return 0.5f * x * (1.0f + erff(x * 0.7071067811865475f));
}

// ---------------- feature transpose: (n,132,H,W) -> (n,H,W,132) --------------
__global__ void transpose_feat_kernel(const float* __restrict__ src,
                                      float* __restrict__ dst,
                                      int Hl, int Wl, int total) {
    int hw = Hl * Wl;
    for (int idx = blockIdx.x * blockDim.x + threadIdx.x; idx < total;
         idx += gridDim.x * blockDim.x) {
        int n = idx / (132 * hw);
        int r = idx - n * 132 * hw;
        int c = r / hw;
        int p = r - c * hw;
        dst[(n * hw + p) * 132 + c] = src[idx];
    }
}

// ---------------- generic direct conv, 4-wide x strips -----------------------
// ACT: 0 = none, 1 = gelu
template<int CIN, int K, int PAD, int ACT>
__global__ void conv_kernel(const float* __restrict__ in,
                            const float* __restrict__ w,
                            const float* __restrict__ bias,
                            const float* __restrict__ resid,
                            float* __restrict__ out, int total) {
    int id = blockIdx.x * blockDim.x + threadIdx.x;
    if (id >= total) return;
    int strip = id % 25;
    int x0 = strip * 4;
    int y = (id / 25) % 100;
    int co = id / 2500;

    float b = bias[co];
    float a0 = b, a1 = b, a2 = b, a3 = b;
    const float* wc = w + (long)co * CIN * K * K;

    for (int ci = 0; ci < CIN; ci++) {
        const float* wci = wc + ci * K * K;
        const float* inc = in + ci * HW;
        #pragma unroll
        for (int ky = 0; ky < K; ky++) {
            int yy = y + ky - PAD;
            if (yy < 0 || yy >= 100) continue;
            const float* row = inc + yy * 100;
            float vin[K + 3];
            #pragma unroll
            for (int j = 0; j < K + 3; j++) {
                int xx = x0 - PAD + j;
                vin[j] = (xx >= 0 && xx < 100) ? row[xx] : 0.0f;
            }
            #pragma unroll
            for (int kx = 0; kx < K; kx++) {
                float wv = wci[ky * K + kx];
                a0 = fmaf(wv, vin[kx + 0], a0);
                a1 = fmaf(wv, vin[kx + 1], a1);
                a2 = fmaf(wv, vin[kx + 2], a2);
                a3 = fmaf(wv, vin[kx + 3], a3);
            }
        }
    }
    int o = (co * 100 + y) * 100 + x0;
    if (resid) {
        a0 += resid[o + 0]; a1 += resid[o + 1];
        a2 += resid[o + 2]; a3 += resid[o + 3];
    }
    if (ACT == 1) {
        a0 = gelu_exact(a0); a1 = gelu_exact(a1);
        a2 = gelu_exact(a2); a3 = gelu_exact(a3);
    }
    out[o + 0] = a0; out[o + 1] = a1; out[o + 2] = a2; out[o + 3] = a3;
}

// ---------------- instance norm over (H,W) per channel -----------------------
__global__ void inorm_kernel(const float* __restrict__ in, float* __restrict__ out) {
    int c = blockIdx.x;
    int tid = threadIdx.x;
    const float* p = in + c * HW;
    __shared__ float r1[256], r2[256];
    __shared__ float mS, invS;
    float s = 0.f, s2 = 0.f;
    for (int i = tid; i < HW; i += 256) {
        float v = p[i];
        s += v;
        s2 = fmaf(v, v, s2);
    }
    r1[tid] = s; r2[tid] = s2;
    __syncthreads();
    for (int st = 128; st > 0; st >>= 1) {
        if (tid < st) { r1[tid] += r1[tid + st]; r2[tid] += r2[tid + st]; }
        __syncthreads();
    }
    if (tid == 0) {
        float m = r1[0] * 1e-4f;
        float v = r2[0] * 1e-4f - m * m;
        mS = m;
        invS = rsqrtf(v + 1e-5f);
    }
    __syncthreads();
    float m = mS, inv = invS;
    float* q = out + c * HW;
    for (int i = tid; i < HW; i += 256) q[i] = (p[i] - m) * inv;
}

// ---------------- offset/sample-weight heads + ref points --------------------
__global__ void offsw_kernel(const float* __restrict__ q,
                             const float* __restrict__ off_w,
                             const float* __restrict__ off_b,
                             const float* __restrict__ sw_w,
                             const float* __restrict__ sw_b,
                             const float* __restrict__ bev_pos,
                             float* __restrict__ ref_out,
                             float* __restrict__ sw_out) {
    int pix = blockIdx.x;
    int tid = threadIdx.x;
    __shared__ float qv[128];
    __shared__ float logit[56];
    for (int c = tid; c < 128; c += 64) qv[c] = q[c * HW + pix];
    __syncthreads();
    if (tid < 24) {
        float s = off_b[tid];
        const float* wr = off_w + tid * 128;
        for (int c = 0; c < 128; c++) s = fmaf(qv[c], wr[c], s);
        logit[tid] = s;
    } else if (tid < 56) {
        int j = tid - 24;
        float s = sw_b[j];
        const float* wr = sw_w + j * 128;
        for (int c = 0; c < 128; c++) s = fmaf(qv[c], wr[c], s);
        logit[tid] = s;
    }
    __syncthreads();
    if (tid < 8) {
        int p = tid;
        const float lo[3] = {-50.f, -50.f, -5.f};
        const float span[3] = {100.f, 100.f, 8.f};
        const float rng = 0.25f + 1e-6f;
        const float zr = 4.0f + 1e-6f;
        #pragma unroll
        for (int d = 0; d < 3; d++) {
            float o = logit[p * 3 + d];
            float s = 1.0f / (1.0f + expf(-o));
            float off = (d < 2) ? (s * rng * 2.0f - rng) : (s * zr * 2.0f - zr);
            float r = bev_pos[pix * 3 + d] * span[d] + lo[d] + off;
            ref_out[pix * 24 + p * 3 + d] = r;
        }
        // softmax over L=4
        float l0 = logit[24 + p * 4 + 0], l1 = logit[24 + p * 4 + 1];
        float l2 = logit[24 + p * 4 + 2], l3 = logit[24 + p * 4 + 3];
        float mx = fmaxf(fmaxf(l0, l1), fmaxf(l2, l3));
        float e0 = expf(l0 - mx), e1 = expf(l1 - mx);
        float e2 = expf(l2 - mx), e3 = expf(l3 - mx);
        float inv = 1.0f / (e0 + e1 + e2 + e3);
        sw_out[pix * 32 + p * 4 + 0] = e0 * inv;
        sw_out[pix * 32 + p * 4 + 1] = e1 * inv;
        sw_out[pix * 32 + p * 4 + 2] = e2 * inv;
        sw_out[pix * 32 + p * 4 + 3] = e3 * inv;
    }
}

// ---------------- projection + bilinear sampling + fold ----------------------
__global__ void sample_kernel(const float* __restrict__ featT,
                              const float* __restrict__ ref,
                              const float* __restrict__ swl,
                              const float* __restrict__ lidar2img,
                              float* __restrict__ sf) {
    int pix = blockIdx.x;
    int tid = threadIdx.x;
    __shared__ float Mm[96];
    __shared__ float refs[24];
    __shared__ float sws[32];
    __shared__ float pos3d[3];
    if (tid < 96) Mm[tid] = lidar2img[tid];
    if (tid < 24) refs[tid] = ref[pix * 24 + tid];
    if (tid < 32) sws[tid] = swl[pix * 32 + tid];
    __syncthreads();

    const int LH[4] = {32, 16, 8, 4};
    const int LW[4] = {88, 44, 22, 11};
    const int LOFF[4] = {L0_OFF, L1_OFF, L2_OFF, L3_OFF};

    float sfeat = 0.f, sweight = 0.f;
    for (int p = 0; p < 8; p++) {
        float acc = 0.f, acc3 = 0.f;
        float rx = refs[p * 3 + 0], ry = refs[p * 3 + 1], rz = refs[p * 3 + 2];
        for (int n = 0; n < 6; n++) {
            const float* M = Mm + n * 16;
            float cz = M[8] * rx + M[9] * ry + M[10] * rz + M[11];
            if (cz <= 1e-5f) continue;
            float cx = (M[0] * rx + M[1] * ry + M[2] * rz + M[3]) / cz;
            float cy = (M[4] * rx + M[5] * ry + M[6] * rz + M[7]) / cz;
            float gx = cx / 704.0f * 2.0f - 1.0f;
            float gy = cy / 256.0f * 2.0f - 1.0f;
            #pragma unroll
            for (int l = 0; l < 4; l++) {
                float wl = sws[p * 4 + l];
                float fx = (gx + 1.0f) * 0.5f * LW[l] - 0.5f;
                float fy = (gy + 1.0f) * 0.5f * LH[l] - 0.5f;
                float x0f = floorf(fx), y0f = floorf(fy);
                float wx = fx - x0f, wy = fy - y0f;
                int ix = (int)x0f, iy = (int)y0f;
                float w00 = (1.f - wx) * (1.f - wy) * wl;
                float w10 = wx * (1.f - wy) * wl;
                float w01 = (1.f - wx) * wy * wl;
                float w11 = wx * wy * wl;
                #pragma unroll
                for (int t = 0; t < 4; t++) {
                    int xi = ix + (t & 1);
                    int yi = iy + (t >> 1);
                    float cw = (t == 0) ? w00 : (t == 1) ? w10 : (t == 2) ? w01 : w11;
                    if (xi >= 0 && xi < LW[l] && yi >= 0 && yi < LH[l]) {
                        const float* fp =
                            featT + LOFF[l] + ((long)(n * LH[l] + yi) * LW[l] + xi) * 132;
                        acc = fmaf(cw, fp[tid], acc);
                        if (tid < 3) acc3 = fmaf(cw, fp[128 + tid], acc3);
                    }
                }
            }
        }
        if (tid < 3) pos3d[tid] = acc3;
        __syncthreads();
        float dx = rx - pos3d[0], dy = ry - pos3d[1], dz = rz - pos3d[2];
        float wgt = expf(-0.1f * (dx * dx + dy * dy + dz * dz));
        sfeat += acc;
        sweight += acc * wgt;
        __syncthreads();
    }
    sf[tid * HW + pix] = sfeat;
    sf[(128 + tid) * HW + pix] = sweight;
}

// =============================================================================
extern "C" void kernel_launch(void* const* d_in, const int* in_sizes, int n_in,
                              void* d_out, int out_size) {
    const float* bev_query = (const float*)d_in[0];
    const float* bev_pos   = (const float*)d_in[1];
    const float* lidar2img = (const float*)d_in[2];
    const float* feat0 = (const float*)d_in[3];
    const float* feat1 = (const float*)d_in[4];
    const float* feat2 = (const float*)d_in[5];
    const float* feat3 = (const float*)d_in[6];
    const float* in_w  = (const float*)d_in[7];
    const float* in_b  = (const float*)d_in[8];
    const float* off_w = (const float*)d_in[9];
    const float* off_b = (const float*)d_in[10];
    const float* sw_w  = (const float*)d_in[11];
    const float* sw_b  = (const float*)d_in[12];
    const float* mid_w1 = (const float*)d_in[13];
    const float* mid_b1 = (const float*)d_in[14];
    const float* mid_w2 = (const float*)d_in[15];
    const float* mid_b2 = (const float*)d_in[16];
    const float* mid_w3 = (const float*)d_in[17];
    const float* mid_b3 = (const float*)d_in[18];
    const float* out_w = (const float*)d_in[19];
    const float* out_b = (const float*)d_in[20];
    float* out = (float*)d_out;

    float *buf, *q, *refp, *swp, *featT, *sf, *m1, *m2;
    cudaGetSymbolAddress((void**)&buf, g_buf);
    cudaGetSymbolAddress((void**)&q, g_q);
    cudaGetSymbolAddress((void**)&refp, g_ref);
    cudaGetSymbolAddress((void**)&swp, g_swl);
    cudaGetSymbolAddress((void**)&featT, g_featT);
    cudaGetSymbolAddress((void**)&sf, g_sf);
    cudaGetSymbolAddress((void**)&m1, g_m1);
    cudaGetSymbolAddress((void**)&m2, g_m2);

    // stage 1: q = bev_query + conv5x5(bev_query); inorm
    {
        int total = 128 * 2500;
        conv_kernel<128, 5, 2, 0><<<(total + 127) / 128, 128>>>(
            bev_query, in_w, in_b, bev_query, buf, total);
        inorm_kernel<<<128, 256>>>(buf, q);
    }

    // stage 2: offset & weight heads
    offsw_kernel<<<HW, 64>>>(q, off_w, off_b, sw_w, sw_b, bev_pos, refp, swp);

    // stage 3: transpose features to channel-last
    {
        int t0 = 6 * 132 * 32 * 88;
        int t1 = 6 * 132 * 16 * 44;
        int t2 = 6 * 132 * 8 * 22;
        int t3 = 6 * 132 * 4 * 11;
        transpose_feat_kernel<<<(t0 + 255) / 256, 256>>>(feat0, featT + L0_OFF, 32, 88, t0);
        transpose_feat_kernel<<<(t1 + 255) / 256, 256>>>(feat1, featT + L1_OFF, 16, 44, t1);
        transpose_feat_kernel<<<(t2 + 255) / 256, 256>>>(feat2, featT + L2_OFF, 8, 22, t2);
        transpose_feat_kernel<<<(t3 + 255) / 256, 256>>>(feat3, featT + L3_OFF, 4, 11, t3);
    }

    // stage 4: projection + sampling + fold -> sf (256,100,100)
    sample_kernel<<<HW, 128>>>(featT, refp, swp, lidar2img, sf);

    // stage 5: mid convs
    {
        int total = 512 * 2500;
        conv_kernel<256, 3, 1, 1><<<(total + 127) / 128, 128>>>(
            sf, mid_w1, mid_b1, nullptr, m1, total);
        conv_kernel<512, 1, 0, 1><<<(total + 127) / 128, 128>>>(
            m1, mid_w2, mid_b2, nullptr, m2, total);
        int total3 = 128 * 2500;
        conv_kernel<512, 3, 1, 0><<<(total3 + 127) / 128, 128>>>(
            m2, mid_w3, mid_b3, q, buf, total3);
        inorm_kernel<<<128, 256>>>(buf, q);
    }

    // stage 6: out conv + final norm
    {
        int total = 128 * 2500;
        conv_kernel<128, 5, 2, 0><<<(total + 127) / 128, 128>>>(
            q, out_w, out_b, q, buf, total);
        inorm_kernel<<<128, 256>>>(buf, out);
    }
}

// round 2
// speedup vs baseline: 3.0931x; 3.0931x over previous
#include <cuda_runtime.h>
#include <cuda_bf16.h>
#include <math.h>

#define HW 10000

// ---------------- scratch (static device globals; no allocation) -------------
__device__ float g_buf[1280000];   // conv outputs pre-norm (128ch)
__device__ float g_q[1280000];     // q after instance norm
__device__ float g_ref[240000];    // (hw, 8, 3) reference points
__device__ float g_swl[320000];    // (hw, 8, 4) softmax weights
__device__ float g_featT[2962080]; // channel-last features, 4 levels concat
__device__ float g_sf[2560000];    // folded features (256, 100, 100)
__device__ float g_m1[5120000];    // mid conv1 out (512ch)
__device__ float g_m2[5120000];    // mid conv2 out (512ch)
// transposed weights [ci*KK+t][co]
__device__ float g_w1T[409600];    // in_w   128x128x25
__device__ float g_w2T[1179648];   // mid_w1 512x256x9
__device__ float g_w3T[262144];    // mid_w2 512x512x1
__device__ float g_w4T[589824];    // mid_w3 128x512x9
__device__ float g_w5T[409600];    // out_w  128x128x25

#define L0_OFF 0
#define L1_OFF 2230272
#define L2_OFF 2787840
#define L3_OFF 2927232

typedef unsigned long long ull;

__device__ __forceinline__ float gelu_exact(float x) {
    return 0.5f * x * (1.0f + erff(x * 0.7071067811865475f));
}

__device__ __forceinline__ ull pk2(float lo, float hi) {
    ull r;
    asm("mov.b64 %0, {%1, %2};" : "=l"(r) : "f"(lo), "f"(hi));
    return r;
}
__device__ __forceinline__ ull dup2(float v) {
    ull r;
    asm("mov.b64 %0, {%1, %1};" : "=l"(r) : "f"(v));
    return r;
}
__device__ __forceinline__ void fma2(ull& acc, ull a, ull b) {
    asm("fma.rn.f32x2 %0, %1, %2, %0;" : "+l"(acc) : "l"(a), "l"(b));
}
__device__ __forceinline__ float2 upk2(ull v) {
    float2 r;
    asm("mov.b64 {%0, %1}, %2;" : "=f"(r.x), "=f"(r.y) : "l"(v));
    return r;
}

// ---------------- weight transpose: [co][ci*KK+t] -> [ci*KK+t][co] -----------
__global__ void wtrans_kernel(const float* __restrict__ w, float* __restrict__ wT,
                              int CO, int CINKK) {
    int total = CO * CINKK;
    for (int idx = blockIdx.x * blockDim.x + threadIdx.x; idx < total;
         idx += gridDim.x * blockDim.x) {
        int co = idx / CINKK;
        int t = idx - co * CINKK;
        wT[t * CO + co] = w[idx];
    }
}

// ---------------- feature transpose: (n,132,H,W) -> (n,H,W,132) --------------
__global__ void transpose_feat_kernel(const float* __restrict__ src,
                                      float* __restrict__ dst,
                                      int Hl, int Wl, int total) {
    int hw = Hl * Wl;
    for (int idx = blockIdx.x * blockDim.x + threadIdx.x; idx < total;
         idx += gridDim.x * blockDim.x) {
        int n = idx / (132 * hw);
        int r = idx - n * 132 * hw;
        int c = r / hw;
        int p = r - c * hw;
        dst[(n * hw + p) * 132 + c] = src[idx];
    }
}

// ---------------- tiled conv with f32x2 FMA ----------------------------------
// Output tile: 64 co x (2 rows x 32 cols). 128 threads = 8 co-groups x 16 px-groups.
// Each thread: 8 cos x 4 px (= 8 f32x2 accumulators x ... 16 pairs total).
// Weights read from transposed layout [ci*KK+t][CO] via LDG.128 (L1-hot).
// Input staged to smem per ci-chunk.
// ACT: 0 none, 1 gelu. resid may be null.
template<int CIN, int CO, int K, int PAD, int ACT, int CICH>
__global__ void __launch_bounds__(128, 4)
conv_tile_kernel(const float* __restrict__ in,
                 const float* __restrict__ wT,
                 const float* __restrict__ bias,
                 const float* __restrict__ resid,
                 float* __restrict__ out) {
    constexpr int KK = K * K;
    constexpr int INW = 32 + 2 * PAD;
    constexpr int ROWS = 2 + 2 * PAD;
    constexpr int STR = (K == 1) ? 32 : (INW | 1);   // odd stride kills conflicts
    __shared__ float s_in[CICH * ROWS * STR];

    int tid = threadIdx.x;
    int cogrp = tid >> 4;         // 0..7
    int pxg = tid & 15;           // 0..15
    int r = pxg >> 3;             // 0..1
    int xq = (pxg & 7) * 4;       // 0,4,..,28
    int bx = blockIdx.x;          // 0..199
    int xbase = (bx & 3) * 32;
    int y0 = (bx >> 2) * 2;
    int coBase = blockIdx.y * 64 + cogrp * 8;

    ull acc[8][2];
    #pragma unroll
    for (int j = 0; j < 8; j++) { acc[j][0] = 0ULL; acc[j][1] = 0ULL; }

    for (int ci0 = 0; ci0 < CIN; ci0 += CICH) {
        __syncthreads();
        // stage input chunk
        for (int idx = tid; idx < CICH * ROWS * INW; idx += 128) {
            int cil = idx / (ROWS * INW);
            int rem = idx - cil * (ROWS * INW);
            int rr = rem / INW;
            int cc = rem - rr * INW;
            int gy = y0 + rr - PAD;
            int gx = xbase + cc - PAD;
            float v = 0.0f;
            if (gy >= 0 && gy < 100 && gx >= 0 && gx < 100)
                v = in[(ci0 + cil) * HW + gy * 100 + gx];
            s_in[cil * ROWS * STR + rr * STR + cc] = v;
        }
        __syncthreads();

        for (int cil = 0; cil < CICH; cil++) {
            const float* srow = s_in + cil * ROWS * STR;
            const float* wrow = wT + (long)(ci0 + cil) * KK * CO + coBase;
            #pragma unroll
            for (int ky = 0; ky < K; ky++) {
                float vin[K + 3];
                #pragma unroll
                for (int j = 0; j < K + 3; j++)
                    vin[j] = srow[(r + ky) * STR + xq + j];
                #pragma unroll
                for (int kx = 0; kx < K; kx++) {
                    float4 wa = *(const float4*)(wrow + (ky * K + kx) * CO);
                    float4 wb = *(const float4*)(wrow + (ky * K + kx) * CO + 4);
                    ull p0 = pk2(vin[kx], vin[kx + 1]);
                    ull p1 = pk2(vin[kx + 2], vin[kx + 3]);
                    ull d;
                    d = dup2(wa.x); fma2(acc[0][0], p0, d); fma2(acc[0][1], p1, d);
                    d = dup2(wa.y); fma2(acc[1][0], p0, d); fma2(acc[1][1], p1, d);
                    d = dup2(wa.z); fma2(acc[2][0], p0, d); fma2(acc[2][1], p1, d);
                    d = dup2(wa.w); fma2(acc[3][0], p0, d); fma2(acc[3][1], p1, d);
                    d = dup2(wb.x); fma2(acc[4][0], p0, d); fma2(acc[4][1], p1, d);
                    d = dup2(wb.y); fma2(acc[5][0], p0, d); fma2(acc[5][1], p1, d);
                    d = dup2(wb.z); fma2(acc[6][0], p0, d); fma2(acc[6][1], p1, d);
                    d = dup2(wb.w); fma2(acc[7][0], p0, d); fma2(acc[7][1], p1, d);
                }
            }
        }
    }

    int x0 = xbase + xq;
    if (x0 >= 100) return;
    int orow = y0 + r;
    #pragma unroll
    for (int j = 0; j < 8; j++) {
        int co = coBase + j;
        float b = bias[co];
        float2 v0 = upk2(acc[j][0]);
        float2 v1 = upk2(acc[j][1]);
        float o0 = v0.x + b, o1 = v0.y + b, o2 = v1.x + b, o3 = v1.y + b;
        long off = (long)co * HW + orow * 100 + x0;
        if (resid) {
            float4 rs = *(const float4*)(resid + off);
            o0 += rs.x; o1 += rs.y; o2 += rs.z; o3 += rs.w;
        }
        if (ACT == 1) {
            o0 = gelu_exact(o0); o1 = gelu_exact(o1);
            o2 = gelu_exact(o2); o3 = gelu_exact(o3);
        }
        float4 ov = make_float4(o0, o1, o2, o3);
        *(float4*)(out + off) = ov;
    }
}

// ---------------- instance norm over (H,W) per channel -----------------------
__global__ void inorm_kernel(const float* __restrict__ in, float* __restrict__ out) {
    int c = blockIdx.x;
    int tid = threadIdx.x;
    const float* p = in + c * HW;
    __shared__ float r1[256], r2[256];
    __shared__ float mS, invS;
    float s = 0.f, s2 = 0.f;
    const float4* p4 = (const float4*)p;
    for (int i = tid; i < 2500; i += 256) {
        float4 v = p4[i];
        s += v.x + v.y + v.z + v.w;
        s2 = fmaf(v.x, v.x, s2); s2 = fmaf(v.y, v.y, s2);
        s2 = fmaf(v.z, v.z, s2); s2 = fmaf(v.w, v.w, s2);
    }
    r1[tid] = s; r2[tid] = s2;
    __syncthreads();
    for (int st = 128; st > 0; st >>= 1) {
        if (tid < st) { r1[tid] += r1[tid + st]; r2[tid] += r2[tid + st]; }
        __syncthreads();
    }
    if (tid == 0) {
        float m = r1[0] * 1e-4f;
        float v = r2[0] * 1e-4f - m * m;
        mS = m;
        invS = rsqrtf(v + 1e-5f);
    }
    __syncthreads();
    float m = mS, inv = invS;
    float4* q4 = (float4*)(out + c * HW);
    for (int i = tid; i < 2500; i += 256) {
        float4 v = p4[i];
        v.x = (v.x - m) * inv; v.y = (v.y - m) * inv;
        v.z = (v.z - m) * inv; v.w = (v.w - m) * inv;
        q4[i] = v;
    }
}

// ---------------- offset/sample-weight heads + ref points --------------------
__global__ void offsw_kernel(const float* __restrict__ q,
                             const float* __restrict__ off_w,
                             const float* __restrict__ off_b,
                             const float* __restrict__ sw_w,
                             const float* __restrict__ sw_b,
                             const float* __restrict__ bev_pos,
                             float* __restrict__ ref_out,
                             float* __restrict__ sw_out) {
    int pix = blockIdx.x;
    int tid = threadIdx.x;
    __shared__ float qv[128];
    __shared__ float logit[56];
    for (int c = tid; c < 128; c += 64) qv[c] = q[c * HW + pix];
    __syncthreads();
    if (tid < 24) {
        float s = off_b[tid];
        const float* wr = off_w + tid * 128;
        for (int c = 0; c < 128; c++) s = fmaf(qv[c], wr[c], s);
        logit[tid] = s;
    } else if (tid < 56) {
        int j = tid - 24;
        float s = sw_b[j];
        const float* wr = sw_w + j * 128;
        for (int c = 0; c < 128; c++) s = fmaf(qv[c], wr[c], s);
        logit[tid] = s;
    }
    __syncthreads();
    if (tid < 8) {
        int p = tid;
        const float lo[3] = {-50.f, -50.f, -5.f};
        const float span[3] = {100.f, 100.f, 8.f};
        const float rng = 0.25f + 1e-6f;
        const float zr = 4.0f + 1e-6f;
        #pragma unroll
        for (int d = 0; d < 3; d++) {
            float o = logit[p * 3 + d];
            float s = 1.0f / (1.0f + expf(-o));
            float off = (d < 2) ? (s * rng * 2.0f - rng) : (s * zr * 2.0f - zr);
            float r = bev_pos[pix * 3 + d] * span[d] + lo[d] + off;
            ref_out[pix * 24 + p * 3 + d] = r;
        }
        float l0 = logit[24 + p * 4 + 0], l1 = logit[24 + p * 4 + 1];
        float l2 = logit[24 + p * 4 + 2], l3 = logit[24 + p * 4 + 3];
        float mx = fmaxf(fmaxf(l0, l1), fmaxf(l2, l3));
        float e0 = expf(l0 - mx), e1 = expf(l1 - mx);
        float e2 = expf(l2 - mx), e3 = expf(l3 - mx);
        float inv = 1.0f / (e0 + e1 + e2 + e3);
        sw_out[pix * 32 + p * 4 + 0] = e0 * inv;
        sw_out[pix * 32 + p * 4 + 1] = e1 * inv;
        sw_out[pix * 32 + p * 4 + 2] = e2 * inv;
        sw_out[pix * 32 + p * 4 + 3] = e3 * inv;
    }
}

// ---------------- projection + bilinear sampling + fold ----------------------
__global__ void sample_kernel(const float* __restrict__ featT,
                              const float* __restrict__ ref,
                              const float* __restrict__ swl,
                              const float* __restrict__ lidar2img,
                              float* __restrict__ sf) {
    int pix = blockIdx.x;
    int tid = threadIdx.x;
    __shared__ float Mm[96];
    __shared__ float refs[24];
    __shared__ float sws[32];
    __shared__ float pos3d[3];
    if (tid < 96) Mm[tid] = lidar2img[tid];
    if (tid < 24) refs[tid] = ref[pix * 24 + tid];
    if (tid < 32) sws[tid] = swl[pix * 32 + tid];
    __syncthreads();

    const int LH[4] = {32, 16, 8, 4};
    const int LW[4] = {88, 44, 22, 11};
    const int LOFF[4] = {L0_OFF, L1_OFF, L2_OFF, L3_OFF};

    float sfeat = 0.f, sweight = 0.f;
    for (int p = 0; p < 8; p++) {
        float acc = 0.f, acc3 = 0.f;
        float rx = refs[p * 3 + 0], ry = refs[p * 3 + 1], rz = refs[p * 3 + 2];
        for (int n = 0; n < 6; n++) {
            const float* M = Mm + n * 16;
            float cz = M[8] * rx + M[9] * ry + M[10] * rz + M[11];
            if (cz <= 1e-5f) continue;
            float cx = (M[0] * rx + M[1] * ry + M[2] * rz + M[3]) / cz;
            float cy = (M[4] * rx + M[5] * ry + M[6] * rz + M[7]) / cz;
            float gx = cx / 704.0f * 2.0f - 1.0f;
            float gy = cy / 256.0f * 2.0f - 1.0f;
            #pragma unroll
            for (int l = 0; l < 4; l++) {
                float wl = sws[p * 4 + l];
                float fx = (gx + 1.0f) * 0.5f * LW[l] - 0.5f;
                float fy = (gy + 1.0f) * 0.5f * LH[l] - 0.5f;
                float x0f = floorf(fx), y0f = floorf(fy);
                float wx = fx - x0f, wy = fy - y0f;
                int ix = (int)x0f, iy = (int)y0f;
                float w00 = (1.f - wx) * (1.f - wy) * wl;
                float w10 = wx * (1.f - wy) * wl;
                float w01 = (1.f - wx) * wy * wl;
                float w11 = wx * wy * wl;
                #pragma unroll
                for (int t = 0; t < 4; t++) {
                    int xi = ix + (t & 1);
                    int yi = iy + (t >> 1);
                    float cw = (t == 0) ? w00 : (t == 1) ? w10 : (t == 2) ? w01 : w11;
                    if (xi >= 0 && xi < LW[l] && yi >= 0 && yi < LH[l]) {
                        const float* fp =
                            featT + LOFF[l] + ((long)(n * LH[l] + yi) * LW[l] + xi) * 132;
                        acc = fmaf(cw, fp[tid], acc);
                        if (tid < 3) acc3 = fmaf(cw, fp[128 + tid], acc3);
                    }
                }
            }
        }
        if (tid < 3) pos3d[tid] = acc3;
        __syncthreads();
        float dx = rx - pos3d[0], dy = ry - pos3d[1], dz = rz - pos3d[2];
        float wgt = expf(-0.1f * (dx * dx + dy * dy + dz * dz));
        sfeat += acc;
        sweight += acc * wgt;
        __syncthreads();
    }
    sf[tid * HW + pix] = sfeat;
    sf[(128 + tid) * HW + pix] = sweight;
}

// =============================================================================
extern "C" void kernel_launch(void* const* d_in, const int* in_sizes, int n_in,
                              void* d_out, int out_size) {
    const float* bev_query = (const float*)d_in[0];
    const float* bev_pos   = (const float*)d_in[1];
    const float* lidar2img = (const float*)d_in[2];
    const float* feat0 = (const float*)d_in[3];
    const float* feat1 = (const float*)d_in[4];
    const float* feat2 = (const float*)d_in[5];
    const float* feat3 = (const float*)d_in[6];
    const float* in_w  = (const float*)d_in[7];
    const float* in_b  = (const float*)d_in[8];
    const float* off_w = (const float*)d_in[9];
    const float* off_b = (const float*)d_in[10];
    const float* sw_w  = (const float*)d_in[11];
    const float* sw_b  = (const float*)d_in[12];
    const float* mid_w1 = (const float*)d_in[13];
    const float* mid_b1 = (const float*)d_in[14];
    const float* mid_w2 = (const float*)d_in[15];
    const float* mid_b2 = (const float*)d_in[16];
    const float* mid_w3 = (const float*)d_in[17];
    const float* mid_b3 = (const float*)d_in[18];
    const float* out_w = (const float*)d_in[19];
    const float* out_b = (const float*)d_in[20];
    float* out = (float*)d_out;

    float *buf, *q, *refp, *swp, *featT, *sf, *m1, *m2;
    float *w1T, *w2T, *w3T, *w4T, *w5T;
    cudaGetSymbolAddress((void**)&buf, g_buf);
    cudaGetSymbolAddress((void**)&q, g_q);
    cudaGetSymbolAddress((void**)&refp, g_ref);
    cudaGetSymbolAddress((void**)&swp, g_swl);
    cudaGetSymbolAddress((void**)&featT, g_featT);
    cudaGetSymbolAddress((void**)&sf, g_sf);
    cudaGetSymbolAddress((void**)&m1, g_m1);
    cudaGetSymbolAddress((void**)&m2, g_m2);
    cudaGetSymbolAddress((void**)&w1T, g_w1T);
    cudaGetSymbolAddress((void**)&w2T, g_w2T);
    cudaGetSymbolAddress((void**)&w3T, g_w3T);
    cudaGetSymbolAddress((void**)&w4T, g_w4T);
    cudaGetSymbolAddress((void**)&w5T, g_w5T);

    // weight transposes (independent; run up front)
    wtrans_kernel<<<512, 256>>>(in_w, w1T, 128, 128 * 25);
    wtrans_kernel<<<512, 256>>>(mid_w1, w2T, 512, 256 * 9);
    wtrans_kernel<<<512, 256>>>(mid_w2, w3T, 512, 512);
    wtrans_kernel<<<512, 256>>>(mid_w3, w4T, 128, 512 * 9);
    wtrans_kernel<<<512, 256>>>(out_w, w5T, 128, 128 * 25);

    // feature transpose to channel-last
    {
        int t0 = 6 * 132 * 32 * 88;
        int t1 = 6 * 132 * 16 * 44;
        int t2 = 6 * 132 * 8 * 22;
        int t3 = 6 * 132 * 4 * 11;
        transpose_feat_kernel<<<(t0 + 255) / 256, 256>>>(feat0, featT + L0_OFF, 32, 88, t0);
        transpose_feat_kernel<<<(t1 + 255) / 256, 256>>>(feat1, featT + L1_OFF, 16, 44, t1);
        transpose_feat_kernel<<<(t2 + 255) / 256, 256>>>(feat2, featT + L2_OFF, 8, 22, t2);
        transpose_feat_kernel<<<(t3 + 255) / 256, 256>>>(feat3, featT + L3_OFF, 4, 11, t3);
    }

    // stage 1: q = bev_query + conv5x5(bev_query); inorm
    conv_tile_kernel<128, 128, 5, 2, 0, 16><<<dim3(200, 2), 128>>>(
        bev_query, w1T, in_b, bev_query, buf);
    inorm_kernel<<<128, 256>>>(buf, q);

    // stage 2: offset & weight heads
    offsw_kernel<<<HW, 64>>>(q, off_w, off_b, sw_w, sw_b, bev_pos, refp, swp);

    // stage 4: projection + sampling + fold -> sf (256,100,100)
    sample_kernel<<<HW, 128>>>(featT, refp, swp, lidar2img, sf);

    // stage 5: mid convs
    conv_tile_kernel<256, 512, 3, 1, 1, 16><<<dim3(200, 8), 128>>>(
        sf, w2T, mid_b1, nullptr, m1);
    conv_tile_kernel<512, 512, 1, 0, 1, 32><<<dim3(200, 8), 128>>>(
        m1, w3T, mid_b2, nullptr, m2);
    conv_tile_kernel<512, 128, 3, 1, 0, 16><<<dim3(200, 2), 128>>>(
        m2, w4T, mid_b3, q, buf);
    inorm_kernel<<<128, 256>>>(buf, q);

    // stage 6: out conv + final norm
    conv_tile_kernel<128, 128, 5, 2, 0, 16><<<dim3(200, 2), 128>>>(
        q, out_w == nullptr ? out_w : w5T, out_b, q, buf);
    inorm_kernel<<<128, 256>>>(buf, out);
}

// round 3
// speedup vs baseline: 3.2133x; 1.0389x over previous
#include <cuda_runtime.h>
#include <cuda_bf16.h>
#include <math.h>

#define HW 10000

// ---------------- scratch (static device globals; no allocation) -------------
__device__ float g_buf[1280000];   // conv outputs pre-norm (128ch)
__device__ float g_q[1280000];     // q after instance norm
__device__ float g_ref[240000];    // (hw, 8, 3) reference points
__device__ float g_swl[320000];    // (hw, 8, 4) softmax weights
__device__ float g_featT[2962080]; // channel-last features, 4 levels concat
__device__ float g_sf[2560000];    // folded features (256, 100, 100)
__device__ float g_m1[5120000];    // mid conv1 out (512ch)
__device__ float g_m2[5120000];    // mid conv2 out (512ch)
// transposed weights [ci*KK+t][co]
__device__ float g_w1T[409600];    // in_w   128x128x25
__device__ float g_w2T[1179648];   // mid_w1 512x256x9
__device__ float g_w3T[262144];    // mid_w2 512x512x1
__device__ float g_w4T[589824];    // mid_w3 128x512x9
__device__ float g_w5T[409600];    // out_w  128x128x25

#define L0_OFF 0
#define L1_OFF 2230272
#define L2_OFF 2787840
#define L3_OFF 2927232

typedef unsigned long long ull;

__device__ __forceinline__ float gelu_exact(float x) {
    return 0.5f * x * (1.0f + erff(x * 0.7071067811865475f));
}

__device__ __forceinline__ ull pk2(float lo, float hi) {
    ull r;
    asm("mov.b64 %0, {%1, %2};" : "=l"(r) : "f"(lo), "f"(hi));
    return r;
}
__device__ __forceinline__ ull dup2(float v) {
    ull r;
    asm("mov.b64 %0, {%1, %1};" : "=l"(r) : "f"(v));
    return r;
}
__device__ __forceinline__ void fma2(ull& acc, ull a, ull b) {
    asm("fma.rn.f32x2 %0, %1, %2, %0;" : "+l"(acc) : "l"(a), "l"(b));
}
__device__ __forceinline__ float2 upk2(ull v) {
    float2 r;
    asm("mov.b64 {%0, %1}, %2;" : "=f"(r.x), "=f"(r.y) : "l"(v));
    return r;
}

// ---------------- weight transpose: [co][ci*KK+t] -> [ci*KK+t][co] -----------
__global__ void wtrans_kernel(const float* __restrict__ w, float* __restrict__ wT,
                              int CO, int CINKK) {
    int total = CO * CINKK;
    for (int idx = blockIdx.x * blockDim.x + threadIdx.x; idx < total;
         idx += gridDim.x * blockDim.x) {
        int co = idx / CINKK;
        int t = idx - co * CINKK;
        wT[t * CO + co] = w[idx];
    }
}

// ---------------- feature transpose: (n,132,H,W) -> (n,H,W,132) --------------
__global__ void transpose_feat_kernel(const float* __restrict__ src,
                                      float* __restrict__ dst,
                                      int Hl, int Wl, int total) {
    int hw = Hl * Wl;
    for (int idx = blockIdx.x * blockDim.x + threadIdx.x; idx < total;
         idx += gridDim.x * blockDim.x) {
        int n = idx / (132 * hw);
        int r = idx - n * 132 * hw;
        int c = r / hw;
        int p = r - c * hw;
        dst[(n * hw + p) * 132 + c] = src[idx];
    }
}

// ---------------- tiled conv with f32x2 FMA ----------------------------------
// Output tile: 64 co x (2 rows x 32 cols). 128 threads = 8 co-groups x 16 px-groups.
// Each thread: 8 cos x 4 px (= 8 f32x2 accumulators x ... 16 pairs total).
// Weights read from transposed layout [ci*KK+t][CO] via LDG.128 (L1-hot).
// Input staged to smem per ci-chunk.
// ACT: 0 none, 1 gelu. resid may be null.
template<int CIN, int CO, int K, int PAD, int ACT, int CICH>
__global__ void __launch_bounds__(128, 4)
conv_tile_kernel(const float* __restrict__ in,
                 const float* __restrict__ wT,
                 const float* __restrict__ bias,
                 const float* __restrict__ resid,
                 float* __restrict__ out) {
    constexpr int KK = K * K;
    constexpr int INW = 32 + 2 * PAD;
    constexpr int ROWS = 2 + 2 * PAD;
    constexpr int STR = (K == 1) ? 32 : (INW | 1);   // odd stride kills conflicts
    __shared__ float s_in[CICH * ROWS * STR];

    int tid = threadIdx.x;
    int cogrp = tid >> 4;         // 0..7
    int pxg = tid & 15;           // 0..15
    int r = pxg >> 3;             // 0..1
    int xq = (pxg & 7) * 4;       // 0,4,..,28
    int bx = blockIdx.x;          // 0..199
    int xbase = (bx & 3) * 32;
    int y0 = (bx >> 2) * 2;
    int coBase = blockIdx.y * 64 + cogrp * 8;

    ull acc[8][2];
    #pragma unroll
    for (int j = 0; j < 8; j++) { acc[j][0] = 0ULL; acc[j][1] = 0ULL; }

    for (int ci0 = 0; ci0 < CIN; ci0 += CICH) {
        __syncthreads();
        // stage input chunk
        for (int idx = tid; idx < CICH * ROWS * INW; idx += 128) {
            int cil = idx / (ROWS * INW);
            int rem = idx - cil * (ROWS * INW);
            int rr = rem / INW;
            int cc = rem - rr * INW;
            int gy = y0 + rr - PAD;
            int gx = xbase + cc - PAD;
            float v = 0.0f;
            if (gy >= 0 && gy < 100 && gx >= 0 && gx < 100)
                v = in[(ci0 + cil) * HW + gy * 100 + gx];
            s_in[cil * ROWS * STR + rr * STR + cc] = v;
        }
        __syncthreads();

        for (int cil = 0; cil < CICH; cil++) {
            const float* srow = s_in + cil * ROWS * STR;
            const float* wrow = wT + (long)(ci0 + cil) * KK * CO + coBase;
            #pragma unroll
            for (int ky = 0; ky < K; ky++) {
                float vin[K + 3];
                #pragma unroll
                for (int j = 0; j < K + 3; j++)
                    vin[j] = srow[(r + ky) * STR + xq + j];
                #pragma unroll
                for (int kx = 0; kx < K; kx++) {
                    float4 wa = *(const float4*)(wrow + (ky * K + kx) * CO);
                    float4 wb = *(const float4*)(wrow + (ky * K + kx) * CO + 4);
                    ull p0 = pk2(vin[kx], vin[kx + 1]);
                    ull p1 = pk2(vin[kx + 2], vin[kx + 3]);
                    ull d;
                    d = dup2(wa.x); fma2(acc[0][0], p0, d); fma2(acc[0][1], p1, d);
                    d = dup2(wa.y); fma2(acc[1][0], p0, d); fma2(acc[1][1], p1, d);
                    d = dup2(wa.z); fma2(acc[2][0], p0, d); fma2(acc[2][1], p1, d);
                    d = dup2(wa.w); fma2(acc[3][0], p0, d); fma2(acc[3][1], p1, d);
                    d = dup2(wb.x); fma2(acc[4][0], p0, d); fma2(acc[4][1], p1, d);
                    d = dup2(wb.y); fma2(acc[5][0], p0, d); fma2(acc[5][1], p1, d);
                    d = dup2(wb.z); fma2(acc[6][0], p0, d); fma2(acc[6][1], p1, d);
                    d = dup2(wb.w); fma2(acc[7][0], p0, d); fma2(acc[7][1], p1, d);
                }
            }
        }
    }

    int x0 = xbase + xq;
    if (x0 >= 100) return;
    int orow = y0 + r;
    #pragma unroll
    for (int j = 0; j < 8; j++) {
        int co = coBase + j;
        float b = bias[co];
        float2 v0 = upk2(acc[j][0]);
        float2 v1 = upk2(acc[j][1]);
        float o0 = v0.x + b, o1 = v0.y + b, o2 = v1.x + b, o3 = v1.y + b;
        long off = (long)co * HW + orow * 100 + x0;
        if (resid) {
            float4 rs = *(const float4*)(resid + off);
            o0 += rs.x; o1 += rs.y; o2 += rs.z; o3 += rs.w;
        }
        if (ACT == 1) {
            o0 = gelu_exact(o0); o1 = gelu_exact(o1);
            o2 = gelu_exact(o2); o3 = gelu_exact(o3);
        }
        float4 ov = make_float4(o0, o1, o2, o3);
        *(float4*)(out + off) = ov;
    }
}

// ---------------- instance norm over (H,W) per channel -----------------------
__global__ void inorm_kernel(const float* __restrict__ in, float* __restrict__ out) {
    int c = blockIdx.x;
    int tid = threadIdx.x;
    const float* p = in + c * HW;
    __shared__ float r1[256], r2[256];
    __shared__ float mS, invS;
    float s = 0.f, s2 = 0.f;
    const float4* p4 = (const float4*)p;
    for (int i = tid; i < 2500; i += 256) {
        float4 v = p4[i];
        s += v.x + v.y + v.z + v.w;
        s2 = fmaf(v.x, v.x, s2); s2 = fmaf(v.y, v.y, s2);
        s2 = fmaf(v.z, v.z, s2); s2 = fmaf(v.w, v.w, s2);
    }
    r1[tid] = s; r2[tid] = s2;
    __syncthreads();
    for (int st = 128; st > 0; st >>= 1) {
        if (tid < st) { r1[tid] += r1[tid + st]; r2[tid] += r2[tid + st]; }
        __syncthreads();
    }
    if (tid == 0) {
        float m = r1[0] * 1e-4f;
        float v = r2[0] * 1e-4f - m * m;
        mS = m;
        invS = rsqrtf(v + 1e-5f);
    }
    __syncthreads();
    float m = mS, inv = invS;
    float4* q4 = (float4*)(out + c * HW);
    for (int i = tid; i < 2500; i += 256) {
        float4 v = p4[i];
        v.x = (v.x - m) * inv; v.y = (v.y - m) * inv;
        v.z = (v.z - m) * inv; v.w = (v.w - m) * inv;
        q4[i] = v;
    }
}

// ---------------- offset/sample-weight heads + ref points --------------------
__global__ void offsw_kernel(const float* __restrict__ q,
                             const float* __restrict__ off_w,
                             const float* __restrict__ off_b,
                             const float* __restrict__ sw_w,
                             const float* __restrict__ sw_b,
                             const float* __restrict__ bev_pos,
                             float* __restrict__ ref_out,
                             float* __restrict__ sw_out) {
    int pix = blockIdx.x;
    int tid = threadIdx.x;
    __shared__ float qv[128];
    __shared__ float logit[56];
    for (int c = tid; c < 128; c += 64) qv[c] = q[c * HW + pix];
    __syncthreads();
    if (tid < 24) {
        float s = off_b[tid];
        const float* wr = off_w + tid * 128;
        for (int c = 0; c < 128; c++) s = fmaf(qv[c], wr[c], s);
        logit[tid] = s;
    } else if (tid < 56) {
        int j = tid - 24;
        float s = sw_b[j];
        const float* wr = sw_w + j * 128;
        for (int c = 0; c < 128; c++) s = fmaf(qv[c], wr[c], s);
        logit[tid] = s;
    }
    __syncthreads();
    if (tid < 8) {
        int p = tid;
        const float lo[3] = {-50.f, -50.f, -5.f};
        const float span[3] = {100.f, 100.f, 8.f};
        const float rng = 0.25f + 1e-6f;
        const float zr = 4.0f + 1e-6f;
        #pragma unroll
        for (int d = 0; d < 3; d++) {
            float o = logit[p * 3 + d];
            float s = 1.0f / (1.0f + expf(-o));
            float off = (d < 2) ? (s * rng * 2.0f - rng) : (s * zr * 2.0f - zr);
            float r = bev_pos[pix * 3 + d] * span[d] + lo[d] + off;
            ref_out[pix * 24 + p * 3 + d] = r;
        }
        float l0 = logit[24 + p * 4 + 0], l1 = logit[24 + p * 4 + 1];
        float l2 = logit[24 + p * 4 + 2], l3 = logit[24 + p * 4 + 3];
        float mx = fmaxf(fmaxf(l0, l1), fmaxf(l2, l3));
        float e0 = expf(l0 - mx), e1 = expf(l1 - mx);
        float e2 = expf(l2 - mx), e3 = expf(l3 - mx);
        float inv = 1.0f / (e0 + e1 + e2 + e3);
        sw_out[pix * 32 + p * 4 + 0] = e0 * inv;
        sw_out[pix * 32 + p * 4 + 1] = e1 * inv;
        sw_out[pix * 32 + p * 4 + 2] = e2 * inv;
        sw_out[pix * 32 + p * 4 + 3] = e3 * inv;
    }
}

// ---------------- projection + bilinear sampling + fold ----------------------
__global__ void sample_kernel(const float* __restrict__ featT,
                              const float* __restrict__ ref,
                              const float* __restrict__ swl,
                              const float* __restrict__ lidar2img,
                              float* __restrict__ sf) {
    int pix = blockIdx.x;
    int tid = threadIdx.x;
    __shared__ float Mm[96];
    __shared__ float refs[24];
    __shared__ float sws[32];
    __shared__ float pos3d[3];
    if (tid < 96) Mm[tid] = lidar2img[tid];
    if (tid < 24) refs[tid] = ref[pix * 24 + tid];
    if (tid < 32) sws[tid] = swl[pix * 32 + tid];
    __syncthreads();

    const int LH[4] = {32, 16, 8, 4};
    const int LW[4] = {88, 44, 22, 11};
    const int LOFF[4] = {L0_OFF, L1_OFF, L2_OFF, L3_OFF};

    float sfeat = 0.f, sweight = 0.f;
    for (int p = 0; p < 8; p++) {
        float acc = 0.f, acc3 = 0.f;
        float rx = refs[p * 3 + 0], ry = refs[p * 3 + 1], rz = refs[p * 3 + 2];
        for (int n = 0; n < 6; n++) {
            const float* M = Mm + n * 16;
            float cz = M[8] * rx + M[9] * ry + M[10] * rz + M[11];
            if (cz <= 1e-5f) continue;
            float cx = (M[0] * rx + M[1] * ry + M[2] * rz + M[3]) / cz;
            float cy = (M[4] * rx + M[5] * ry + M[6] * rz + M[7]) / cz;
            float gx = cx / 704.0f * 2.0f - 1.0f;
            float gy = cy / 256.0f * 2.0f - 1.0f;
            #pragma unroll
            for (int l = 0; l < 4; l++) {
                float wl = sws[p * 4 + l];
                float fx = (gx + 1.0f) * 0.5f * LW[l] - 0.5f;
                float fy = (gy + 1.0f) * 0.5f * LH[l] - 0.5f;
                float x0f = floorf(fx), y0f = floorf(fy);
                float wx = fx - x0f, wy = fy - y0f;
                int ix = (int)x0f, iy = (int)y0f;
                float w00 = (1.f - wx) * (1.f - wy) * wl;
                float w10 = wx * (1.f - wy) * wl;
                float w01 = (1.f - wx) * wy * wl;
                float w11 = wx * wy * wl;
                #pragma unroll
                for (int t = 0; t < 4; t++) {
                    int xi = ix + (t & 1);
                    int yi = iy + (t >> 1);
                    float cw = (t == 0) ? w00 : (t == 1) ? w10 : (t == 2) ? w01 : w11;
                    if (xi >= 0 && xi < LW[l] && yi >= 0 && yi < LH[l]) {
                        const float* fp =
                            featT + LOFF[l] + ((long)(n * LH[l] + yi) * LW[l] + xi) * 132;
                        acc = fmaf(cw, fp[tid], acc);
                        if (tid < 3) acc3 = fmaf(cw, fp[128 + tid], acc3);
                    }
                }
            }
        }
        if (tid < 3) pos3d[tid] = acc3;
        __syncthreads();
        float dx = rx - pos3d[0], dy = ry - pos3d[1], dz = rz - pos3d[2];
        float wgt = expf(-0.1f * (dx * dx + dy * dy + dz * dz));
        sfeat += acc;
        sweight += acc * wgt;
        __syncthreads();
    }
    sf[tid * HW + pix] = sfeat;
    sf[(128 + tid) * HW + pix] = sweight;
}

// =============================================================================
extern "C" void kernel_launch(void* const* d_in, const int* in_sizes, int n_in,
                              void* d_out, int out_size) {
    const float* bev_query = (const float*)d_in[0];
    const float* bev_pos   = (const float*)d_in[1];
    const float* lidar2img = (const float*)d_in[2];
    const float* feat0 = (const float*)d_in[3];
    const float* feat1 = (const float*)d_in[4];
    const float* feat2 = (const float*)d_in[5];
    const float* feat3 = (const float*)d_in[6];
    const float* in_w  = (const float*)d_in[7];
    const float* in_b  = (const float*)d_in[8];
    const float* off_w = (const float*)d_in[9];
    const float* off_b = (const float*)d_in[10];
    const float* sw_w  = (const float*)d_in[11];
    const float* sw_b  = (const float*)d_in[12];
    const float* mid_w1 = (const float*)d_in[13];
    const float* mid_b1 = (const float*)d_in[14];
    const float* mid_w2 = (const float*)d_in[15];
    const float* mid_b2 = (const float*)d_in[16];
    const float* mid_w3 = (const float*)d_in[17];
    const float* mid_b3 = (const float*)d_in[18];
    const float* out_w = (const float*)d_in[19];
    const float* out_b = (const float*)d_in[20];
    float* out = (float*)d_out;

    float *buf, *q, *refp, *swp, *featT, *sf, *m1, *m2;
    float *w1T, *w2T, *w3T, *w4T, *w5T;
    cudaGetSymbolAddress((void**)&buf, g_buf);
    cudaGetSymbolAddress((void**)&q, g_q);
    cudaGetSymbolAddress((void**)&refp, g_ref);
    cudaGetSymbolAddress((void**)&swp, g_swl);
    cudaGetSymbolAddress((void**)&featT, g_featT);
    cudaGetSymbolAddress((void**)&sf, g_sf);
    cudaGetSymbolAddress((void**)&m1, g_m1);
    cudaGetSymbolAddress((void**)&m2, g_m2);
    cudaGetSymbolAddress((void**)&w1T, g_w1T);
    cudaGetSymbolAddress((void**)&w2T, g_w2T);
    cudaGetSymbolAddress((void**)&w3T, g_w3T);
    cudaGetSymbolAddress((void**)&w4T, g_w4T);
    cudaGetSymbolAddress((void**)&w5T, g_w5T);

    // weight transposes (independent; run up front)
    wtrans_kernel<<<512, 256>>>(in_w, w1T, 128, 128 * 25);
    wtrans_kernel<<<512, 256>>>(mid_w1, w2T, 512, 256 * 9);
    wtrans_kernel<<<512, 256>>>(mid_w2, w3T, 512, 512);
    wtrans_kernel<<<512, 256>>>(mid_w3, w4T, 128, 512 * 9);
    wtrans_kernel<<<512, 256>>>(out_w, w5T, 128, 128 * 25);

    // feature transpose to channel-last
    {
        int t0 = 6 * 132 * 32 * 88;
        int t1 = 6 * 132 * 16 * 44;
        int t2 = 6 * 132 * 8 * 22;
        int t3 = 6 * 132 * 4 * 11;
        transpose_feat_kernel<<<(t0 + 255) / 256, 256>>>(feat0, featT + L0_OFF, 32, 88, t0);
        transpose_feat_kernel<<<(t1 + 255) / 256, 256>>>(feat1, featT + L1_OFF, 16, 44, t1);
        transpose_feat_kernel<<<(t2 + 255) / 256, 256>>>(feat2, featT + L2_OFF, 8, 22, t2);
        transpose_feat_kernel<<<(t3 + 255) / 256, 256>>>(feat3, featT + L3_OFF, 4, 11, t3);
    }

    // stage 1: q = bev_query + conv5x5(bev_query); inorm
    conv_tile_kernel<128, 128, 5, 2, 0, 16><<<dim3(200, 2), 128>>>(
        bev_query, w1T, in_b, bev_query, buf);
    inorm_kernel<<<128, 256>>>(buf, q);

    // stage 2: offset & weight heads
    offsw_kernel<<<HW, 64>>>(q, off_w, off_b, sw_w, sw_b, bev_pos, refp, swp);

    // stage 4: projection + sampling + fold -> sf (256,100,100)
    sample_kernel<<<HW, 128>>>(featT, refp, swp, lidar2img, sf);

    // stage 5: mid convs
    conv_tile_kernel<256, 512, 3, 1, 1, 16><<<dim3(200, 8), 128>>>(
        sf, w2T, mid_b1, nullptr, m1);
    conv_tile_kernel<512, 512, 1, 0, 1, 32><<<dim3(200, 8), 128>>>(
        m1, w3T, mid_b2, nullptr, m2);
    conv_tile_kernel<512, 128, 3, 1, 0, 16><<<dim3(200, 2), 128>>>(
        m2, w4T, mid_b3, q, buf);
    inorm_kernel<<<128, 256>>>(buf, q);

    // stage 6: out conv + final norm
    conv_tile_kernel<128, 128, 5, 2, 0, 16><<<dim3(200, 2), 128>>>(
        q, out_w == nullptr ? out_w : w5T, out_b, q, buf);
    inorm_kernel<<<128, 256>>>(buf, out);
}

// round 5
// speedup vs baseline: 3.6129x; 1.1244x over previous
#include <cuda_runtime.h>
#include <cuda_bf16.h>
#include <math.h>
#include <stdint.h>

#define HW 10000
#define PW 104
#define PPX (PW*PW)

__device__ float g_buf[1280000];
__device__ float g_q[1280000];
__device__ float g_q2[1280000];
__device__ float g_sf[2560000];
__device__ float g_m1[5120000];
__device__ float g_m2[5120000];
__device__ float g_ref[240000];
__device__ float g_swl[320000];
__device__ float g_featT[2962080];
__device__ float g_part[51200];
__device__ float g_mv[256];

__device__ unsigned short g_bqp_h[PPX*128], g_bqp_l[PPX*128];
__device__ unsigned short g_sfp_h[PPX*256], g_sfp_l[PPX*256];
__device__ unsigned short g_m1p_h[PPX*512], g_m1p_l[PPX*512];
__device__ unsigned short g_m2p_h[PPX*512], g_m2p_l[PPX*512];
__device__ unsigned short g_q2p_h[PPX*128], g_q2p_l[PPX*128];
__device__ unsigned short g_w1_h[409600],  g_w1_l[409600];
__device__ unsigned short g_w2_h[1179648], g_w2_l[1179648];
__device__ unsigned short g_w3_h[262144],  g_w3_l[262144];
__device__ unsigned short g_w4_h[589824],  g_w4_l[589824];
__device__ unsigned short g_w5_h[409600],  g_w5_l[409600];

#define L0_OFF 0
#define L1_OFF 2230272
#define L2_OFF 2787840
#define L3_OFF 2927232

__device__ __forceinline__ float gelu_exact(float x) {
    return 0.5f * x * (1.0f + erff(x * 0.7071067811865475f));
}
__device__ __forceinline__ void split_bf16(float v, unsigned short& h, unsigned short& l) {
    __nv_bfloat16 bh = __float2bfloat16(v);
    float r = v - __bfloat162float(bh);
    __nv_bfloat16 bl = __float2bfloat16(r);
    h = __bfloat16_as_ushort(bh);
    l = __bfloat16_as_ushort(bl);
}
__device__ __forceinline__ void mma_bf16(float* c, const uint32_t* a, uint32_t b0, uint32_t b1) {
    asm volatile(
        "mma.sync.aligned.m16n8k16.row.col.f32.bf16.bf16.f32 "
        "{%0,%1,%2,%3}, {%4,%5,%6,%7}, {%8,%9}, {%0,%1,%2,%3};"
        : "+f"(c[0]), "+f"(c[1]), "+f"(c[2]), "+f"(c[3])
        : "r"(a[0]), "r"(a[1]), "r"(a[2]), "r"(a[3]), "r"(b0), "r"(b1));
}

// weights [co][ci][t] -> [t][co][ci] bf16 hi/lo
__global__ void wprep_kernel(const float* __restrict__ w, unsigned short* __restrict__ wh,
                             unsigned short* __restrict__ wl, int CO, int CIN, int KK) {
    int total = CO * CIN * KK;
    for (int s = blockIdx.x * blockDim.x + threadIdx.x; s < total; s += gridDim.x * blockDim.x) {
        int co = s / (CIN * KK);
        int rem = s - co * (CIN * KK);
        int ci = rem / KK;
        int t = rem - ci * KK;
        unsigned short h, l;
        split_bf16(w[s], h, l);
        long d = ((long)t * CO + co) * CIN + ci;
        wh[d] = h; wl[d] = l;
    }
}

__global__ void padsplit_cm_kernel(const float* __restrict__ src,
                                   unsigned short* __restrict__ dh, unsigned short* __restrict__ dl) {
    int ppx = blockIdx.x;
    int c = threadIdx.x;
    int py = ppx / PW, px = ppx % PW;
    int y = py - 2, x = px - 2;
    float v = 0.0f;
    if (y >= 0 && y < 100 && x >= 0 && x < 100) v = src[c * HW + y * 100 + x];
    unsigned short h, l;
    split_bf16(v, h, l);
    dh[(long)ppx * 128 + c] = h;
    dl[(long)ppx * 128 + c] = l;
}

__global__ void padsplit_cl_kernel(const float* __restrict__ src,
                                   unsigned short* __restrict__ dh, unsigned short* __restrict__ dl, int C) {
    int ppx = blockIdx.x;
    int c = blockIdx.y * 128 + threadIdx.x;
    int py = ppx / PW, px = ppx % PW;
    int y = py - 2, x = px - 2;
    float v = 0.0f;
    if (y >= 0 && y < 100 && x >= 0 && x < 100) v = src[(long)(y * 100 + x) * C + c];
    unsigned short h, l;
    split_bf16(v, h, l);
    dh[(long)ppx * C + c] = h;
    dl[(long)ppx * C + c] = l;
}

__global__ void transpose_feat_kernel(const float* __restrict__ src, float* __restrict__ dst,
                                      int Hl, int Wl, int total) {
    int hw = Hl * Wl;
    for (int idx = blockIdx.x * blockDim.x + threadIdx.x; idx < total; idx += gridDim.x * blockDim.x) {
        int n = idx / (132 * hw);
        int r = idx - n * 132 * hw;
        int c = r / hw;
        int p = r - c * hw;
        dst[(n * hw + p) * 132 + c] = src[idx];
    }
}

// implicit-GEMM conv: block 128co x 112px (2 rows x 56), 4 warps x 32co
// RES: 0 none, 1 channel-last, 2 channel-major
template<int CIN, int CO, int K, int PAD, int ACT, int RES>
__global__ void __launch_bounds__(128)
conv_mma_kernel(const unsigned short* __restrict__ inp_h, const unsigned short* __restrict__ inp_l,
                const unsigned short* __restrict__ w_h, const unsigned short* __restrict__ w_l,
                const float* __restrict__ bias, const float* __restrict__ resid,
                float* __restrict__ out) {
    constexpr int KK = K * K;
    constexpr int XW = 56 + (K - 1);
    constexpr int RWS = 2 + (K - 1);
    constexpr int NPX = RWS * XW;
    constexpr int PA = 2 - PAD;
    constexpr int RWRD = CIN >> 1;

    __shared__ uint32_t s_h[NPX * 12];
    __shared__ uint32_t s_l[NPX * 12];

    int tid = threadIdx.x;
    int warp = tid >> 5;
    int lane = tid & 31;
    int lq = lane & 3;
    int lr = lane >> 2;

    int nb = blockIdx.x;
    int y0 = (nb >> 1) * 2;
    int x0 = (nb & 1) * 56;
    int coB = blockIdx.y * 128 + warp * 32;

    const uint32_t* Wh = (const uint32_t*)w_h;
    const uint32_t* Wl = (const uint32_t*)w_l;

    float acc[2][14][4];
    #pragma unroll
    for (int m = 0; m < 2; m++)
        #pragma unroll
        for (int n = 0; n < 14; n++) {
            acc[m][n][0] = 0.f; acc[m][n][1] = 0.f; acc[m][n][2] = 0.f; acc[m][n][3] = 0.f;
        }

    uint32_t ah[2][4], al[2][4], nh[2][4], nl[2][4];

    for (int ch = 0; ch < CIN / 16; ch++) {
        int ci0 = ch * 16;
        __syncthreads();
        for (int p = tid; p < NPX; p += 128) {
            int r = p / XW;
            int xx = p - r * XW;
            int prow = y0 + r + PA;
            int pcol = x0 + xx + PA;
            uint4 vh0, vh1, vl0, vl1;
            if (pcol < PW) {
                const uint4* gh = (const uint4*)(inp_h + ((long)(prow * PW + pcol) * CIN + ci0));
                const uint4* gl = (const uint4*)(inp_l + ((long)(prow * PW + pcol) * CIN + ci0));
                vh0 = gh[0]; vh1 = gh[1]; vl0 = gl[0]; vl1 = gl[1];
            } else {
                vh0 = make_uint4(0,0,0,0); vh1 = vh0; vl0 = vh0; vl1 = vh0;
            }
            *(uint4*)(s_h + p * 12) = vh0;
            *(uint4*)(s_h + p * 12 + 4) = vh1;
            *(uint4*)(s_l + p * 12) = vl0;
            *(uint4*)(s_l + p * 12 + 4) = vl1;
        }
        __syncthreads();

        int kw = (ci0 >> 1) + lq;
        #pragma unroll
        for (int mt = 0; mt < 2; mt++) {
            long rb = ((long)0 * CO + (coB + mt * 16 + lr)) * RWRD + kw;
            ah[mt][0] = Wh[rb];                al[mt][0] = Wl[rb];
            ah[mt][1] = Wh[rb + 8 * RWRD];     al[mt][1] = Wl[rb + 8 * RWRD];
            ah[mt][2] = Wh[rb + 4];            al[mt][2] = Wl[rb + 4];
            ah[mt][3] = Wh[rb + 8 * RWRD + 4]; al[mt][3] = Wl[rb + 8 * RWRD + 4];
        }

        #pragma unroll 1
        for (int tap = 0; tap < KK; tap++) {
            if (tap + 1 < KK) {
                #pragma unroll
                for (int mt = 0; mt < 2; mt++) {
                    long rb = ((long)(tap + 1) * CO + (coB + mt * 16 + lr)) * RWRD + kw;
                    nh[mt][0] = Wh[rb];                nl[mt][0] = Wl[rb];
                    nh[mt][1] = Wh[rb + 8 * RWRD];     nl[mt][1] = Wl[rb + 8 * RWRD];
                    nh[mt][2] = Wh[rb + 4];            nl[mt][2] = Wl[rb + 4];
                    nh[mt][3] = Wh[rb + 8 * RWRD + 4]; nl[mt][3] = Wl[rb + 8 * RWRD + 4];
                }
            }
            int ky = tap / K, kx = tap - ky * K;
            int base = (ky * XW + kx + lr) * 12 + lq;
            #pragma unroll
            for (int nt = 0; nt < 14; nt++) {
                int off = base + ((nt / 7) * XW + (nt % 7) * 8) * 12;
                uint32_t bh0 = s_h[off], bh1 = s_h[off + 4];
                uint32_t bl0 = s_l[off], bl1 = s_l[off + 4];
                #pragma unroll
                for (int mt = 0; mt < 2; mt++) {
                    mma_bf16(acc[mt][nt], ah[mt], bh0, bh1);
                    mma_bf16(acc[mt][nt], ah[mt], bl0, bl1);
                    mma_bf16(acc[mt][nt], al[mt], bh0, bh1);
                }
            }
            if (tap + 1 < KK) {
                #pragma unroll
                for (int mt = 0; mt < 2; mt++)
                    #pragma unroll
                    for (int k = 0; k < 4; k++) { ah[mt][k] = nh[mt][k]; al[mt][k] = nl[mt][k]; }
            }
        }
    }

    #pragma unroll
    for (int mt = 0; mt < 2; mt++) {
        int co0 = coB + mt * 16 + lr;
        float b0 = bias[co0];
        float b8 = bias[co0 + 8];
        #pragma unroll
        for (int nt = 0; nt < 14; nt++) {
            int rr = y0 + nt / 7;
            int xb = x0 + (nt % 7) * 8 + 2 * lq;
            #pragma unroll
            for (int e = 0; e < 2; e++) {
                int x = xb + e;
                if (x >= 100) continue;
                int px = rr * 100 + x;
                float v0 = acc[mt][nt][e] + b0;
                float v8 = acc[mt][nt][2 + e] + b8;
                if (RES == 1) {
                    v0 += resid[(long)px * CO + co0];
                    v8 += resid[(long)px * CO + co0 + 8];
                } else if (RES == 2) {
                    v0 += resid[(long)co0 * HW + px];
                    v8 += resid[(long)(co0 + 8) * HW + px];
                }
                if (ACT == 1) { v0 = gelu_exact(v0); v8 = gelu_exact(v8); }
                out[(long)px * CO + co0] = v0;
                out[(long)px * CO + co0 + 8] = v8;
            }
        }
    }
}

// ---- instance norm (channel-last C=128) ----
__global__ void inorm_part_kernel(const float* __restrict__ in, float* __restrict__ part) {
    int blk = blockIdx.x;
    int tid = threadIdx.x;
    int c = tid & 127;
    int sub = tid >> 7;
    float s = 0.f, s2 = 0.f;
    for (int px = blk * 100 + sub; px < blk * 100 + 100; px += 2) {
        float v = in[(long)px * 128 + c];
        s += v;
        s2 = fmaf(v, v, s2);
    }
    __shared__ float sh1[256], sh2[256];
    sh1[tid] = s; sh2[tid] = s2;
    __syncthreads();
    if (tid < 128) {
        part[blk * 256 + tid] = sh1[tid] + sh1[tid + 128];
        part[blk * 256 + 128 + tid] = sh2[tid] + sh2[tid + 128];
    }
}
__global__ void inorm_final_kernel(const float* __restrict__ part, float* __restrict__ mv) {
    int tid = threadIdx.x;
    float s = 0.f;
    for (int b = 0; b < 100; b++) s += part[b * 256 + tid];
    __shared__ float sh[256];
    sh[tid] = s;
    __syncthreads();
    if (tid < 128) {
        float m = sh[tid] * 1e-4f;
        float v = sh[tid + 128] * 1e-4f - m * m;
        mv[tid] = m;
        mv[128 + tid] = rsqrtf(v + 1e-5f);
    }
}
template<int CM>
__global__ void inorm_apply_kernel(const float* __restrict__ in, const float* __restrict__ mv,
                                   float* __restrict__ out) {
    int px = blockIdx.x;
    int c = threadIdx.x;
    float v = (in[(long)px * 128 + c] - mv[c]) * mv[128 + c];
    if (CM) out[(long)c * HW + px] = v;
    else out[(long)px * 128 + c] = v;
}

__global__ void offsw_kernel(const float* __restrict__ q, const float* __restrict__ off_w,
                             const float* __restrict__ off_b, const float* __restrict__ sw_w,
                             const float* __restrict__ sw_b, const float* __restrict__ bev_pos,
                             float* __restrict__ ref_out, float* __restrict__ sw_out) {
    int pix = blockIdx.x;
    int tid = threadIdx.x;
    __shared__ float qv[128];
    __shared__ float logit[56];
    for (int c = tid; c < 128; c += 64) qv[c] = q[(long)pix * 128 + c];
    __syncthreads();
    if (tid < 24) {
        float s = off_b[tid];
        const float* wr = off_w + tid * 128;
        for (int c = 0; c < 128; c++) s = fmaf(qv[c], wr[c], s);
        logit[tid] = s;
    } else if (tid < 56) {
        int j = tid - 24;
        float s = sw_b[j];
        const float* wr = sw_w + j * 128;
        for (int c = 0; c < 128; c++) s = fmaf(qv[c], wr[c], s);
        logit[tid] = s;
    }
    __syncthreads();
    if (tid < 8) {
        int p = tid;
        const float lo[3] = {-50.f, -50.f, -5.f};
        const float span[3] = {100.f, 100.f, 8.f};
        const float rng = 0.25f + 1e-6f;
        const float zr = 4.0f + 1e-6f;
        #pragma unroll
        for (int d = 0; d < 3; d++) {
            float o = logit[p * 3 + d];
            float s = 1.0f / (1.0f + expf(-o));
            float off = (d < 2) ? (s * rng * 2.0f - rng) : (s * zr * 2.0f - zr);
            ref_out[pix * 24 + p * 3 + d] = bev_pos[pix * 3 + d] * span[d] + lo[d] + off;
        }
        float l0 = logit[24 + p * 4 + 0], l1 = logit[24 + p * 4 + 1];
        float l2 = logit[24 + p * 4 + 2], l3 = logit[24 + p * 4 + 3];
        float mx = fmaxf(fmaxf(l0, l1), fmaxf(l2, l3));
        float e0 = expf(l0 - mx), e1 = expf(l1 - mx);
        float e2 = expf(l2 - mx), e3 = expf(l3 - mx);
        float inv = 1.0f / (e0 + e1 + e2 + e3);
        sw_out[pix * 32 + p * 4 + 0] = e0 * inv;
        sw_out[pix * 32 + p * 4 + 1] = e1 * inv;
        sw_out[pix * 32 + p * 4 + 2] = e2 * inv;
        sw_out[pix * 32 + p * 4 + 3] = e3 * inv;
    }
}

__global__ void sample_kernel(const float* __restrict__ featT, const float* __restrict__ ref,
                              const float* __restrict__ swl, const float* __restrict__ lidar2img,
                              float* __restrict__ sf) {
    int pix = blockIdx.x;
    int tid = threadIdx.x;
    __shared__ float Mm[96];
    __shared__ float refs[24];
    __shared__ float sws[32];
    __shared__ float pos3d[3];
    if (tid < 96) Mm[tid] = lidar2img[tid];
    if (tid < 24) refs[tid] = ref[pix * 24 + tid];
    if (tid < 32) sws[tid] = swl[pix * 32 + tid];
    __syncthreads();

    const int LH[4] = {32, 16, 8, 4};
    const int LW[4] = {88, 44, 22, 11};
    const int LOFF[4] = {L0_OFF, L1_OFF, L2_OFF, L3_OFF};

    float sfeat = 0.f, sweight = 0.f;
    for (int p = 0; p < 8; p++) {
        float acc = 0.f, acc3 = 0.f;
        float rx = refs[p * 3 + 0], ry = refs[p * 3 + 1], rz = refs[p * 3 + 2];
        for (int n = 0; n < 6; n++) {
            const float* M = Mm + n * 16;
            float cz = M[8] * rx + M[9] * ry + M[10] * rz + M[11];
            if (cz <= 1e-5f) continue;
            float cx = (M[0] * rx + M[1] * ry + M[2] * rz + M[3]) / cz;
            float cy = (M[4] * rx + M[5] * ry + M[6] * rz + M[7]) / cz;
            float gx = cx / 704.0f * 2.0f - 1.0f;
            float gy = cy / 256.0f * 2.0f - 1.0f;
            #pragma unroll
            for (int l = 0; l < 4; l++) {
                float wl = sws[p * 4 + l];
                float fx = (gx + 1.0f) * 0.5f * LW[l] - 0.5f;
                float fy = (gy + 1.0f) * 0.5f * LH[l] - 0.5f;
                float x0f = floorf(fx), y0f = floorf(fy);
                float wx = fx - x0f, wy = fy - y0f;
                int ix = (int)x0f, iy = (int)y0f;
                float w00 = (1.f - wx) * (1.f - wy) * wl;
                float w10 = wx * (1.f - wy) * wl;
                float w01 = (1.f - wx) * wy * wl;
                float w11 = wx * wy * wl;
                #pragma unroll
                for (int t = 0; t < 4; t++) {
                    int xi = ix + (t & 1);
                    int yi = iy + (t >> 1);
                    float cw = (t == 0) ? w00 : (t == 1) ? w10 : (t == 2) ? w01 : w11;
                    if (xi >= 0 && xi < LW[l] && yi >= 0 && yi < LH[l]) {
                        const float* fp = featT + LOFF[l] + ((long)(n * LH[l] + yi) * LW[l] + xi) * 132;
                        acc = fmaf(cw, fp[tid], acc);
                        if (tid < 3) acc3 = fmaf(cw, fp[128 + tid], acc3);
                    }
                }
            }
        }
        if (tid < 3) pos3d[tid] = acc3;
        __syncthreads();
        float dx = rx - pos3d[0], dy = ry - pos3d[1], dz = rz - pos3d[2];
        float wgt = expf(-0.1f * (dx * dx + dy * dy + dz * dz));
        sfeat += acc;
        sweight += acc * wgt;
        __syncthreads();
    }
    sf[(long)pix * 256 + tid] = sfeat;
    sf[(long)pix * 256 + 128 + tid] = sweight;
}

extern "C" void kernel_launch(void* const* d_in, const int* in_sizes, int n_in,
                              void* d_out, int out_size) {
    const float* bev_query = (const float*)d_in[0];
    const float* bev_pos   = (const float*)d_in[1];
    const float* lidar2img = (const float*)d_in[2];
    const float* feat0 = (const float*)d_in[3];
    const float* feat1 = (const float*)d_in[4];
    const float* feat2 = (const float*)d_in[5];
    const float* feat3 = (const float*)d_in[6];
    const float* in_w  = (const float*)d_in[7];
    const float* in_b  = (const float*)d_in[8];
    const float* off_w = (const float*)d_in[9];
    const float* off_b = (const float*)d_in[10];
    const float* sw_w  = (const float*)d_in[11];
    const float* sw_b  = (const float*)d_in[12];
    const float* mid_w1 = (const float*)d_in[13];
    const float* mid_b1 = (const float*)d_in[14];
    const float* mid_w2 = (const float*)d_in[15];
    const float* mid_b2 = (const float*)d_in[16];
    const float* mid_w3 = (const float*)d_in[17];
    const float* mid_b3 = (const float*)d_in[18];
    const float* out_w = (const float*)d_in[19];
    const float* out_b = (const float*)d_in[20];
    float* out = (float*)d_out;

    float *buf, *q, *q2, *sf, *m1, *m2, *refp, *swp, *featT, *part, *mv;
    cudaGetSymbolAddress((void**)&buf, g_buf);
    cudaGetSymbolAddress((void**)&q, g_q);
    cudaGetSymbolAddress((void**)&q2, g_q2);
    cudaGetSymbolAddress((void**)&sf, g_sf);
    cudaGetSymbolAddress((void**)&m1, g_m1);
    cudaGetSymbolAddress((void**)&m2, g_m2);
    cudaGetSymbolAddress((void**)&refp, g_ref);
    cudaGetSymbolAddress((void**)&swp, g_swl);
    cudaGetSymbolAddress((void**)&featT, g_featT);
    cudaGetSymbolAddress((void**)&part, g_part);
    cudaGetSymbolAddress((void**)&mv, g_mv);

    unsigned short *bqph,*bqpl,*sfph,*sfpl,*m1ph,*m1pl,*m2ph,*m2pl,*q2ph,*q2pl;
    unsigned short *w1h,*w1l,*w2h,*w2l,*w3h,*w3l,*w4h,*w4l,*w5h,*w5l;
    cudaGetSymbolAddress((void**)&bqph, g_bqp_h); cudaGetSymbolAddress((void**)&bqpl, g_bqp_l);
    cudaGetSymbolAddress((void**)&sfph, g_sfp_h); cudaGetSymbolAddress((void**)&sfpl, g_sfp_l);
    cudaGetSymbolAddress((void**)&m1ph, g_m1p_h); cudaGetSymbolAddress((void**)&m1pl, g_m1p_l);
    cudaGetSymbolAddress((void**)&m2ph, g_m2p_h); cudaGetSymbolAddress((void**)&m2pl, g_m2p_l);
    cudaGetSymbolAddress((void**)&q2ph, g_q2p_h); cudaGetSymbolAddress((void**)&q2pl, g_q2p_l);
    cudaGetSymbolAddress((void**)&w1h, g_w1_h); cudaGetSymbolAddress((void**)&w1l, g_w1_l);
    cudaGetSymbolAddress((void**)&w2h, g_w2_h); cudaGetSymbolAddress((void**)&w2l, g_w2_l);
    cudaGetSymbolAddress((void**)&w3h, g_w3_h); cudaGetSymbolAddress((void**)&w3l, g_w3_l);
    cudaGetSymbolAddress((void**)&w4h, g_w4_h); cudaGetSymbolAddress((void**)&w4l, g_w4_l);
    cudaGetSymbolAddress((void**)&w5h, g_w5_h); cudaGetSymbolAddress((void**)&w5l, g_w5_l);

    wprep_kernel<<<256, 256>>>(in_w,  w1h, w1l, 128, 128, 25);
    wprep_kernel<<<512, 256>>>(mid_w1, w2h, w2l, 512, 256, 9);
    wprep_kernel<<<256, 256>>>(mid_w2, w3h, w3l, 512, 512, 1);
    wprep_kernel<<<256, 256>>>(mid_w3, w4h, w4l, 128, 512, 9);
    wprep_kernel<<<256, 256>>>(out_w, w5h, w5l, 128, 128, 25);
    padsplit_cm_kernel<<<PPX, 128>>>(bev_query, bqph, bqpl);
    {
        int t0 = 6*132*32*88, t1 = 6*132*16*44, t2 = 6*132*8*22, t3 = 6*132*4*11;
        transpose_feat_kernel<<<(t0+255)/256, 256>>>(feat0, featT + L0_OFF, 32, 88, t0);
        transpose_feat_kernel<<<(t1+255)/256, 256>>>(feat1, featT + L1_OFF, 16, 44, t1);
        transpose_feat_kernel<<<(t2+255)/256, 256>>>(feat2, featT + L2_OFF, 8, 22, t2);
        transpose_feat_kernel<<<(t3+255)/256, 256>>>(feat3, featT + L3_OFF, 4, 11, t3);
    }

    // stage1: conv5x5 + resid(bev_query, channel-major) -> buf; inorm -> q
    conv_mma_kernel<128,128,5,2,0,2><<<dim3(100,1), 128>>>(bqph, bqpl, w1h, w1l, in_b, bev_query, buf);
    inorm_part_kernel<<<100, 256>>>(buf, part);
    inorm_final_kernel<<<1, 256>>>(part, mv);
    inorm_apply_kernel<0><<<HW, 128>>>(buf, mv, q);

    offsw_kernel<<<HW, 64>>>(q, off_w, off_b, sw_w, sw_b, bev_pos, refp, swp);
    sample_kernel<<<HW, 128>>>(featT, refp, swp, lidar2img, sf);

    padsplit_cl_kernel<<<dim3(PPX, 2), 128>>>(sf, sfph, sfpl, 256);
    conv_mma_kernel<256,512,3,1,1,0><<<dim3(100,4), 128>>>(sfph, sfpl, w2h, w2l, mid_b1, nullptr, m1);
    padsplit_cl_kernel<<<dim3(PPX, 4), 128>>>(m1, m1ph, m1pl, 512);
    conv_mma_kernel<512,512,1,0,1,0><<<dim3(100,4), 128>>>(m1ph, m1pl, w3h, w3l, mid_b2, nullptr, m2);
    padsplit_cl_kernel<<<dim3(PPX, 4), 128>>>(m2, m2ph, m2pl, 512);
    conv_mma_kernel<512,128,3,1,0,1><<<dim3(100,1), 128>>>(m2ph, m2pl, w4h, w4l, mid_b3, q, buf);
    inorm_part_kernel<<<100, 256>>>(buf, part);
    inorm_final_kernel<<<1, 256>>>(part, mv);
    inorm_apply_kernel<0><<<HW, 128>>>(buf, mv, q2);

    padsplit_cl_kernel<<<dim3(PPX, 1), 128>>>(q2, q2ph, q2pl, 128);
    conv_mma_kernel<128,128,5,2,0,1><<<dim3(100,1), 128>>>(q2ph, q2pl, w5h, w5l, out_b, q2, buf);
    inorm_part_kernel<<<100, 256>>>(buf, part);
    inorm_final_kernel<<<1, 256>>>(part, mv);
    inorm_apply_kernel<1><<<HW, 128>>>(buf, mv, out);
}

// round 6
// speedup vs baseline: 5.5648x; 1.5403x over previous
#include <cuda_runtime.h>
#include <cuda_bf16.h>
#include <math.h>
#include <stdint.h>

#define HW 10000
#define PW 104
#define PPX (PW*PW)

__device__ float g_buf[1280000];
__device__ float g_q[1280000];
__device__ float g_q2[1280000];
__device__ float g_ref[240000];
__device__ float g_swl[320000];
__device__ float g_featT[2962080];
__device__ float g_part[51200];
__device__ float g_mv[256];

__device__ unsigned short g_bqp_h[PPX*128], g_bqp_l[PPX*128];
__device__ unsigned short g_sfp_h[PPX*256], g_sfp_l[PPX*256];
__device__ unsigned short g_m1p_h[PPX*512], g_m1p_l[PPX*512];
__device__ unsigned short g_m2p_h[PPX*512], g_m2p_l[PPX*512];
__device__ unsigned short g_q2p_h[PPX*128], g_q2p_l[PPX*128];
__device__ unsigned short g_w1_h[409600],  g_w1_l[409600];
__device__ unsigned short g_w2_h[1179648], g_w2_l[1179648];
__device__ unsigned short g_w3_h[262144],  g_w3_l[262144];
__device__ unsigned short g_w4_h[589824],  g_w4_l[589824];
__device__ unsigned short g_w5_h[409600],  g_w5_l[409600];

#define L0_OFF 0
#define L1_OFF 2230272
#define L2_OFF 2787840
#define L3_OFF 2927232

__device__ __forceinline__ float gelu_exact(float x) {
    return 0.5f * x * (1.0f + erff(x * 0.7071067811865475f));
}
__device__ __forceinline__ void split_bf16(float v, unsigned short& h, unsigned short& l) {
    __nv_bfloat16 bh = __float2bfloat16(v);
    float r = v - __bfloat162float(bh);
    __nv_bfloat16 bl = __float2bfloat16(r);
    h = __bfloat16_as_ushort(bh);
    l = __bfloat16_as_ushort(bl);
}
__device__ __forceinline__ void mma_bf16(float* c, const uint32_t* a, uint32_t b0, uint32_t b1) {
    asm volatile(
        "mma.sync.aligned.m16n8k16.row.col.f32.bf16.bf16.f32 "
        "{%0,%1,%2,%3}, {%4,%5,%6,%7}, {%8,%9}, {%0,%1,%2,%3};"
        : "+f"(c[0]), "+f"(c[1]), "+f"(c[2]), "+f"(c[3])
        : "r"(a[0]), "r"(a[1]), "r"(a[2]), "r"(a[3]), "r"(b0), "r"(b1));
}

__device__ __forceinline__ void wprep_one(const float* w, unsigned short* wh,
                                          unsigned short* wl, int CO, int CIN, int KK, int s) {
    int co = s / (CIN * KK);
    int rem = s - co * (CIN * KK);
    int ci = rem / KK;
    int t = rem - ci * KK;
    unsigned short h, l;
    split_bf16(w[s], h, l);
    long d = ((long)t * CO + co) * CIN + ci;
    wh[d] = h; wl[d] = l;
}

__global__ void wprep_all(const float* __restrict__ w1, const float* __restrict__ w2,
                          const float* __restrict__ w3, const float* __restrict__ w4,
                          const float* __restrict__ w5,
                          unsigned short* w1h, unsigned short* w1l,
                          unsigned short* w2h, unsigned short* w2l,
                          unsigned short* w3h, unsigned short* w3l,
                          unsigned short* w4h, unsigned short* w4l,
                          unsigned short* w5h, unsigned short* w5l) {
    const int N1 = 409600, N2 = 1179648, N3 = 262144, N4 = 589824, N5 = 409600;
    int idx = blockIdx.x * blockDim.x + threadIdx.x;
    if (idx < N1) wprep_one(w1, w1h, w1l, 128, 128, 25, idx);
    else if (idx < N1 + N2) wprep_one(w2, w2h, w2l, 512, 256, 9, idx - N1);
    else if (idx < N1 + N2 + N3) wprep_one(w3, w3h, w3l, 512, 512, 1, idx - N1 - N2);
    else if (idx < N1 + N2 + N3 + N4) wprep_one(w4, w4h, w4l, 128, 512, 9, idx - N1 - N2 - N3);
    else if (idx < N1 + N2 + N3 + N4 + N5) wprep_one(w5, w5h, w5l, 128, 128, 25, idx - N1 - N2 - N3 - N4);
}

__global__ void padsplit_cm_kernel(const float* __restrict__ src,
                                   unsigned short* __restrict__ dh, unsigned short* __restrict__ dl) {
    int ppx = blockIdx.x;
    int c = threadIdx.x;
    int py = ppx / PW, px = ppx % PW;
    int y = py - 2, x = px - 2;
    float v = 0.0f;
    if (y >= 0 && y < 100 && x >= 0 && x < 100) v = src[c * HW + y * 100 + x];
    unsigned short h, l;
    split_bf16(v, h, l);
    dh[(long)ppx * 128 + c] = h;
    dl[(long)ppx * 128 + c] = l;
}

__device__ __forceinline__ void tpose_one(const float* src, float* dst, int Hl, int Wl, int idx) {
    int hw = Hl * Wl;
    int n = idx / (132 * hw);
    int r = idx - n * 132 * hw;
    int c = r / hw;
    int p = r - c * hw;
    dst[(n * hw + p) * 132 + c] = src[idx];
}

__global__ void transpose_all(const float* __restrict__ f0, const float* __restrict__ f1,
                              const float* __restrict__ f2, const float* __restrict__ f3,
                              float* __restrict__ featT) {
    const int T0 = 2230272, T1 = 557568, T2 = 139392, T3 = 34848;
    int idx = blockIdx.x * blockDim.x + threadIdx.x;
    if (idx < T0) tpose_one(f0, featT + L0_OFF, 32, 88, idx);
    else if (idx < T0 + T1) tpose_one(f1, featT + L1_OFF, 16, 44, idx - T0);
    else if (idx < T0 + T1 + T2) tpose_one(f2, featT + L2_OFF, 8, 22, idx - T0 - T1);
    else if (idx < T0 + T1 + T2 + T3) tpose_one(f3, featT + L3_OFF, 4, 11, idx - T0 - T1 - T2);
}

// implicit-GEMM conv: block tile 128co x (2 rows x 40 px), grid.x = 150 (50 pairs x 3 x-chunks)
// RES: 0 none, 1 channel-last resid, 2 channel-major resid. WF: write fp32. WS: write split padded.
template<int CIN, int CO, int K, int PAD, int ACT, int RES, int WF, int WS>
__global__ void __launch_bounds__(128)
conv_mma_kernel(const unsigned short* __restrict__ inp_h, const unsigned short* __restrict__ inp_l,
                const unsigned short* __restrict__ w_h, const unsigned short* __restrict__ w_l,
                const float* __restrict__ bias, const float* __restrict__ resid,
                float* __restrict__ outf,
                unsigned short* __restrict__ oh, unsigned short* __restrict__ ol) {
    constexpr int KK = K * K;
    constexpr int XW = (40 + (K - 1)) | 1;
    constexpr int RWS = 2 + (K - 1);
    constexpr int NPX = RWS * XW;
    constexpr int PA = 2 - PAD;
    constexpr int RWRD = CIN >> 1;

    __shared__ uint32_t s_h[NPX * 12];
    __shared__ uint32_t s_l[NPX * 12];

    int tid = threadIdx.x;
    int warp = tid >> 5;
    int lane = tid & 31;
    int lq = lane & 3;
    int lr = lane >> 2;

    int nb = blockIdx.x;           // 0..149
    int y0 = (nb / 3) * 2;
    int x0 = (nb % 3) * 40;
    int coB = blockIdx.y * 128 + warp * 32;

    const uint32_t* Wh = (const uint32_t*)w_h;
    const uint32_t* Wl = (const uint32_t*)w_l;

    float acc[2][10][4];
    #pragma unroll
    for (int m = 0; m < 2; m++)
        #pragma unroll
        for (int n = 0; n < 10; n++) {
            acc[m][n][0] = 0.f; acc[m][n][1] = 0.f; acc[m][n][2] = 0.f; acc[m][n][3] = 0.f;
        }

    uint32_t ah[2][4], al[2][4], nh[2][4], nl[2][4];

    for (int ch = 0; ch < CIN / 16; ch++) {
        int ci0 = ch * 16;
        __syncthreads();
        for (int p = tid; p < NPX; p += 128) {
            int r = p / XW;
            int xx = p - r * XW;
            int prow = y0 + r + PA;
            int pcol = x0 + xx + PA;
            uint4 vh0, vh1, vl0, vl1;
            if (pcol < PW) {
                const uint4* gh = (const uint4*)(inp_h + ((long)(prow * PW + pcol) * CIN + ci0));
                const uint4* gl = (const uint4*)(inp_l + ((long)(prow * PW + pcol) * CIN + ci0));
                vh0 = gh[0]; vh1 = gh[1]; vl0 = gl[0]; vl1 = gl[1];
            } else {
                vh0 = make_uint4(0,0,0,0); vh1 = vh0; vl0 = vh0; vl1 = vh0;
            }
            *(uint4*)(s_h + p * 12) = vh0;
            *(uint4*)(s_h + p * 12 + 4) = vh1;
            *(uint4*)(s_l + p * 12) = vl0;
            *(uint4*)(s_l + p * 12 + 4) = vl1;
        }
        __syncthreads();

        int kw = (ci0 >> 1) + lq;
        #pragma unroll
        for (int mt = 0; mt < 2; mt++) {
            long rb = ((long)0 * CO + (coB + mt * 16 + lr)) * RWRD + kw;
            ah[mt][0] = Wh[rb];                al[mt][0] = Wl[rb];
            ah[mt][1] = Wh[rb + 8 * RWRD];     al[mt][1] = Wl[rb + 8 * RWRD];
            ah[mt][2] = Wh[rb + 4];            al[mt][2] = Wl[rb + 4];
            ah[mt][3] = Wh[rb + 8 * RWRD + 4]; al[mt][3] = Wl[rb + 8 * RWRD + 4];
        }

        #pragma unroll 1
        for (int tap = 0; tap < KK; tap++) {
            if (tap + 1 < KK) {
                #pragma unroll
                for (int mt = 0; mt < 2; mt++) {
                    long rb = ((long)(tap + 1) * CO + (coB + mt * 16 + lr)) * RWRD + kw;
                    nh[mt][0] = Wh[rb];                nl[mt][0] = Wl[rb];
                    nh[mt][1] = Wh[rb + 8 * RWRD];     nl[mt][1] = Wl[rb + 8 * RWRD];
                    nh[mt][2] = Wh[rb + 4];            nl[mt][2] = Wl[rb + 4];
                    nh[mt][3] = Wh[rb + 8 * RWRD + 4]; nl[mt][3] = Wl[rb + 8 * RWRD + 4];
                }
            }
            int ky = tap / K, kx = tap - ky * K;
            int base = (ky * XW + kx + lr) * 12 + lq;
            #pragma unroll
            for (int nt = 0; nt < 10; nt++) {
                int off = base + ((nt / 5) * XW + (nt % 5) * 8) * 12;
                uint32_t bh0 = s_h[off], bh1 = s_h[off + 4];
                uint32_t bl0 = s_l[off], bl1 = s_l[off + 4];
                #pragma unroll
                for (int mt = 0; mt < 2; mt++) {
                    mma_bf16(acc[mt][nt], ah[mt], bh0, bh1);
                    mma_bf16(acc[mt][nt], ah[mt], bl0, bl1);
                    mma_bf16(acc[mt][nt], al[mt], bh0, bh1);
                }
            }
            if (tap + 1 < KK) {
                #pragma unroll
                for (int mt = 0; mt < 2; mt++)
                    #pragma unroll
                    for (int k = 0; k < 4; k++) { ah[mt][k] = nh[mt][k]; al[mt][k] = nl[mt][k]; }
            }
        }
    }

    #pragma unroll
    for (int mt = 0; mt < 2; mt++) {
        int co0 = coB + mt * 16 + lr;
        float b0 = bias[co0];
        float b8 = bias[co0 + 8];
        #pragma unroll
        for (int nt = 0; nt < 10; nt++) {
            int rr = y0 + nt / 5;
            int xb = x0 + (nt % 5) * 8 + 2 * lq;
            #pragma unroll
            for (int e = 0; e < 2; e++) {
                int x = xb + e;
                if (x >= 100) continue;
                int px = rr * 100 + x;
                float v0 = acc[mt][nt][e] + b0;
                float v8 = acc[mt][nt][2 + e] + b8;
                if (RES == 1) {
                    v0 += resid[(long)px * CO + co0];
                    v8 += resid[(long)px * CO + co0 + 8];
                } else if (RES == 2) {
                    v0 += resid[(long)co0 * HW + px];
                    v8 += resid[(long)(co0 + 8) * HW + px];
                }
                if (ACT == 1) { v0 = gelu_exact(v0); v8 = gelu_exact(v8); }
                if (WF) {
                    outf[(long)px * CO + co0] = v0;
                    outf[(long)px * CO + co0 + 8] = v8;
                }
                if (WS) {
                    long pp = (long)((rr + 2) * PW + x + 2) * CO;
                    unsigned short h, l;
                    split_bf16(v0, h, l); oh[pp + co0] = h; ol[pp + co0] = l;
                    split_bf16(v8, h, l); oh[pp + co0 + 8] = h; ol[pp + co0 + 8] = l;
                }
            }
        }
    }
}

// ---- instance norm (channel-last C=128) ----
__global__ void inorm_part_kernel(const float* __restrict__ in, float* __restrict__ part) {
    int blk = blockIdx.x;
    int tid = threadIdx.x;
    int c = tid & 127;
    int sub = tid >> 7;
    float s = 0.f, s2 = 0.f;
    for (int px = blk * 100 + sub; px < blk * 100 + 100; px += 2) {
        float v = in[(long)px * 128 + c];
        s += v;
        s2 = fmaf(v, v, s2);
    }
    __shared__ float sh1[256], sh2[256];
    sh1[tid] = s; sh2[tid] = s2;
    __syncthreads();
    if (tid < 128) {
        part[blk * 256 + tid] = sh1[tid] + sh1[tid + 128];
        part[blk * 256 + 128 + tid] = sh2[tid] + sh2[tid + 128];
    }
}
__global__ void inorm_final_kernel(const float* __restrict__ part, float* __restrict__ mv) {
    int tid = threadIdx.x;
    float s = 0.f;
    for (int b = 0; b < 100; b++) s += part[b * 256 + tid];
    __shared__ float sh[256];
    sh[tid] = s;
    __syncthreads();
    if (tid < 128) {
        float m = sh[tid] * 1e-4f;
        float v = sh[tid + 128] * 1e-4f - m * m;
        mv[tid] = m;
        mv[128 + tid] = rsqrtf(v + 1e-5f);
    }
}
// MODE 0: fp32 channel-last. MODE 1: fp32 channel-major. MODE 2: fp32 CL + split padded.
template<int MODE>
__global__ void inorm_apply_kernel(const float* __restrict__ in, const float* __restrict__ mv,
                                   float* __restrict__ out,
                                   unsigned short* __restrict__ oh, unsigned short* __restrict__ ol) {
    int px = blockIdx.x;
    int c = threadIdx.x;
    float v = (in[(long)px * 128 + c] - mv[c]) * mv[128 + c];
    if (MODE == 1) out[(long)c * HW + px] = v;
    else out[(long)px * 128 + c] = v;
    if (MODE == 2) {
        int ppx = (px / 100 + 2) * PW + (px % 100) + 2;
        unsigned short h, l;
        split_bf16(v, h, l);
        oh[(long)ppx * 128 + c] = h;
        ol[(long)ppx * 128 + c] = l;
    }
}

__global__ void offsw_kernel(const float* __restrict__ q, const float* __restrict__ off_w,
                             const float* __restrict__ off_b, const float* __restrict__ sw_w,
                             const float* __restrict__ sw_b, const float* __restrict__ bev_pos,
                             float* __restrict__ ref_out, float* __restrict__ sw_out) {
    int pix = blockIdx.x;
    int tid = threadIdx.x;
    __shared__ float qv[128];
    __shared__ float logit[56];
    for (int c = tid; c < 128; c += 64) qv[c] = q[(long)pix * 128 + c];
    __syncthreads();
    if (tid < 24) {
        float s = off_b[tid];
        const float* wr = off_w + tid * 128;
        for (int c = 0; c < 128; c++) s = fmaf(qv[c], wr[c], s);
        logit[tid] = s;
    } else if (tid < 56) {
        int j = tid - 24;
        float s = sw_b[j];
        const float* wr = sw_w + j * 128;
        for (int c = 0; c < 128; c++) s = fmaf(qv[c], wr[c], s);
        logit[tid] = s;
    }
    __syncthreads();
    if (tid < 8) {
        int p = tid;
        const float lo[3] = {-50.f, -50.f, -5.f};
        const float span[3] = {100.f, 100.f, 8.f};
        const float rng = 0.25f + 1e-6f;
        const float zr = 4.0f + 1e-6f;
        #pragma unroll
        for (int d = 0; d < 3; d++) {
            float o = logit[p * 3 + d];
            float s = 1.0f / (1.0f + expf(-o));
            float off = (d < 2) ? (s * rng * 2.0f - rng) : (s * zr * 2.0f - zr);
            ref_out[pix * 24 + p * 3 + d] = bev_pos[pix * 3 + d] * span[d] + lo[d] + off;
        }
        float l0 = logit[24 + p * 4 + 0], l1 = logit[24 + p * 4 + 1];
        float l2 = logit[24 + p * 4 + 2], l3 = logit[24 + p * 4 + 3];
        float mx = fmaxf(fmaxf(l0, l1), fmaxf(l2, l3));
        float e0 = expf(l0 - mx), e1 = expf(l1 - mx);
        float e2 = expf(l2 - mx), e3 = expf(l3 - mx);
        float inv = 1.0f / (e0 + e1 + e2 + e3);
        sw_out[pix * 32 + p * 4 + 0] = e0 * inv;
        sw_out[pix * 32 + p * 4 + 1] = e1 * inv;
        sw_out[pix * 32 + p * 4 + 2] = e2 * inv;
        sw_out[pix * 32 + p * 4 + 3] = e3 * inv;
    }
}

__global__ void sample_kernel(const float* __restrict__ featT, const float* __restrict__ ref,
                              const float* __restrict__ swl, const float* __restrict__ lidar2img,
                              unsigned short* __restrict__ sfh, unsigned short* __restrict__ sfl) {
    int pix = blockIdx.x;
    int tid = threadIdx.x;
    __shared__ float Mm[96];
    __shared__ float refs[24];
    __shared__ float sws[32];
    __shared__ float pos3d[3];
    if (tid < 96) Mm[tid] = lidar2img[tid];
    if (tid < 24) refs[tid] = ref[pix * 24 + tid];
    if (tid < 32) sws[tid] = swl[pix * 32 + tid];
    __syncthreads();

    const int LH[4] = {32, 16, 8, 4};
    const int LW[4] = {88, 44, 22, 11};
    const int LOFF[4] = {L0_OFF, L1_OFF, L2_OFF, L3_OFF};

    float sfeat = 0.f, sweight = 0.f;
    for (int p = 0; p < 8; p++) {
        float acc = 0.f, acc3 = 0.f;
        float rx = refs[p * 3 + 0], ry = refs[p * 3 + 1], rz = refs[p * 3 + 2];
        for (int n = 0; n < 6; n++) {
            const float* M = Mm + n * 16;
            float cz = M[8] * rx + M[9] * ry + M[10] * rz + M[11];
            if (cz <= 1e-5f) continue;
            float cx = (M[0] * rx + M[1] * ry + M[2] * rz + M[3]) / cz;
            float cy = (M[4] * rx + M[5] * ry + M[6] * rz + M[7]) / cz;
            float gx = cx / 704.0f * 2.0f - 1.0f;
            float gy = cy / 256.0f * 2.0f - 1.0f;
            #pragma unroll
            for (int l = 0; l < 4; l++) {
                float wl = sws[p * 4 + l];
                float fx = (gx + 1.0f) * 0.5f * LW[l] - 0.5f;
                float fy = (gy + 1.0f) * 0.5f * LH[l] - 0.5f;
                float x0f = floorf(fx), y0f = floorf(fy);
                float wx = fx - x0f, wy = fy - y0f;
                int ix = (int)x0f, iy = (int)y0f;
                float w00 = (1.f - wx) * (1.f - wy) * wl;
                float w10 = wx * (1.f - wy) * wl;
                float w01 = (1.f - wx) * wy * wl;
                float w11 = wx * wy * wl;
                #pragma unroll
                for (int t = 0; t < 4; t++) {
                    int xi = ix + (t & 1);
                    int yi = iy + (t >> 1);
                    float cw = (t == 0) ? w00 : (t == 1) ? w10 : (t == 2) ? w01 : w11;
                    if (xi >= 0 && xi < LW[l] && yi >= 0 && yi < LH[l]) {
                        const float* fp = featT + LOFF[l] + ((long)(n * LH[l] + yi) * LW[l] + xi) * 132;
                        acc = fmaf(cw, fp[tid], acc);
                        if (tid < 3) acc3 = fmaf(cw, fp[128 + tid], acc3);
                    }
                }
            }
        }
        if (tid < 3) pos3d[tid] = acc3;
        __syncthreads();
        float dx = rx - pos3d[0], dy = ry - pos3d[1], dz = rz - pos3d[2];
        float wgt = expf(-0.1f * (dx * dx + dy * dy + dz * dz));
        sfeat += acc;
        sweight += acc * wgt;
        __syncthreads();
    }
    int ppx = (pix / 100 + 2) * PW + (pix % 100) + 2;
    unsigned short h, l;
    split_bf16(sfeat, h, l);
    sfh[(long)ppx * 256 + tid] = h;
    sfl[(long)ppx * 256 + tid] = l;
    split_bf16(sweight, h, l);
    sfh[(long)ppx * 256 + 128 + tid] = h;
    sfl[(long)ppx * 256 + 128 + tid] = l;
}

extern "C" void kernel_launch(void* const* d_in, const int* in_sizes, int n_in,
                              void* d_out, int out_size) {
    const float* bev_query = (const float*)d_in[0];
    const float* bev_pos   = (const float*)d_in[1];
    const float* lidar2img = (const float*)d_in[2];
    const float* feat0 = (const float*)d_in[3];
    const float* feat1 = (const float*)d_in[4];
    const float* feat2 = (const float*)d_in[5];
    const float* feat3 = (const float*)d_in[6];
    const float* in_w  = (const float*)d_in[7];
    const float* in_b  = (const float*)d_in[8];
    const float* off_w = (const float*)d_in[9];
    const float* off_b = (const float*)d_in[10];
    const float* sw_w  = (const float*)d_in[11];
    const float* sw_b  = (const float*)d_in[12];
    const float* mid_w1 = (const float*)d_in[13];
    const float* mid_b1 = (const float*)d_in[14];
    const float* mid_w2 = (const float*)d_in[15];
    const float* mid_b2 = (const float*)d_in[16];
    const float* mid_w3 = (const float*)d_in[17];
    const float* mid_b3 = (const float*)d_in[18];
    const float* out_w = (const float*)d_in[19];
    const float* out_b = (const float*)d_in[20];
    float* out = (float*)d_out;

    float *buf, *q, *q2, *refp, *swp, *featT, *part, *mv;
    cudaGetSymbolAddress((void**)&buf, g_buf);
    cudaGetSymbolAddress((void**)&q, g_q);
    cudaGetSymbolAddress((void**)&q2, g_q2);
    cudaGetSymbolAddress((void**)&refp, g_ref);
    cudaGetSymbolAddress((void**)&swp, g_swl);
    cudaGetSymbolAddress((void**)&featT, g_featT);
    cudaGetSymbolAddress((void**)&part, g_part);
    cudaGetSymbolAddress((void**)&mv, g_mv);

    unsigned short *bqph,*bqpl,*sfph,*sfpl,*m1ph,*m1pl,*m2ph,*m2pl,*q2ph,*q2pl;
    unsigned short *w1h,*w1l,*w2h,*w2l,*w3h,*w3l,*w4h,*w4l,*w5h,*w5l;
    cudaGetSymbolAddress((void**)&bqph, g_bqp_h); cudaGetSymbolAddress((void**)&bqpl, g_bqp_l);
    cudaGetSymbolAddress((void**)&sfph, g_sfp_h); cudaGetSymbolAddress((void**)&sfpl, g_sfp_l);
    cudaGetSymbolAddress((void**)&m1ph, g_m1p_h); cudaGetSymbolAddress((void**)&m1pl, g_m1p_l);
    cudaGetSymbolAddress((void**)&m2ph, g_m2p_h); cudaGetSymbolAddress((void**)&m2pl, g_m2p_l);
    cudaGetSymbolAddress((void**)&q2ph, g_q2p_h); cudaGetSymbolAddress((void**)&q2pl, g_q2p_l);
    cudaGetSymbolAddress((void**)&w1h, g_w1_h); cudaGetSymbolAddress((void**)&w1l, g_w1_l);
    cudaGetSymbolAddress((void**)&w2h, g_w2_h); cudaGetSymbolAddress((void**)&w2l, g_w2_l);
    cudaGetSymbolAddress((void**)&w3h, g_w3_h); cudaGetSymbolAddress((void**)&w3l, g_w3_l);
    cudaGetSymbolAddress((void**)&w4h, g_w4_h); cudaGetSymbolAddress((void**)&w4l, g_w4_l);
    cudaGetSymbolAddress((void**)&w5h, g_w5_h); cudaGetSymbolAddress((void**)&w5l, g_w5_l);

    wprep_all<<<(2850816 + 255) / 256, 256>>>(in_w, mid_w1, mid_w2, mid_w3, out_w,
                                              w1h, w1l, w2h, w2l, w3h, w3l, w4h, w4l, w5h, w5l);
    padsplit_cm_kernel<<<PPX, 128>>>(bev_query, bqph, bqpl);
    transpose_all<<<(2962080 + 255) / 256, 256>>>(feat0, feat1, feat2, feat3, featT);

    // stage1: conv5x5 + resid(bev_query, channel-major) -> buf; inorm -> q
    conv_mma_kernel<128,128,5,2,0,2,1,0><<<dim3(150,1), 128>>>(
        bqph, bqpl, w1h, w1l, in_b, bev_query, buf, nullptr, nullptr);
    inorm_part_kernel<<<100, 256>>>(buf, part);
    inorm_final_kernel<<<1, 256>>>(part, mv);
    inorm_apply_kernel<0><<<HW, 128>>>(buf, mv, q, nullptr, nullptr);

    offsw_kernel<<<HW, 64>>>(q, off_w, off_b, sw_w, sw_b, bev_pos, refp, swp);
    sample_kernel<<<HW, 128>>>(featT, refp, swp, lidar2img, sfph, sfpl);

    conv_mma_kernel<256,512,3,1,1,0,0,1><<<dim3(150,4), 128>>>(
        sfph, sfpl, w2h, w2l, mid_b1, nullptr, nullptr, m1ph, m1pl);
    conv_mma_kernel<512,512,1,0,1,0,0,1><<<dim3(150,4), 128>>>(
        m1ph, m1pl, w3h, w3l, mid_b2, nullptr, nullptr, m2ph, m2pl);
    conv_mma_kernel<512,128,3,1,0,1,1,0><<<dim3(150,1), 128>>>(
        m2ph, m2pl, w4h, w4l, mid_b3, q, buf, nullptr, nullptr);
    inorm_part_kernel<<<100, 256>>>(buf, part);
    inorm_final_kernel<<<1, 256>>>(part, mv);
    inorm_apply_kernel<2><<<HW, 128>>>(buf, mv, q2, q2ph, q2pl);

    conv_mma_kernel<128,128,5,2,0,1,1,0><<<dim3(150,1), 128>>>(
        q2ph, q2pl, w5h, w5l, out_b, q2, buf, nullptr, nullptr);
    inorm_part_kernel<<<100, 256>>>(buf, part);
    inorm_final_kernel<<<1, 256>>>(part, mv);
    inorm_apply_kernel<1><<<HW, 128>>>(buf, mv, out, nullptr, nullptr);
}